// round 14
// baseline (speedup 1.0000x reference)
#include <cuda_runtime.h>
#include <cuda_bf16.h>
#include <cstdint>
#include <math.h>

#define BATCH 4
#define LQ 257        // NTOK+1
#define DMODEL 384
#define DIN 768
#define NST 16
#define DTR 24
#define KCONV 4
#define NTOK 256
#define POSI 128
#define BL (BATCH*LQ)   // 1028
#define XR 8            // xproj row tile

// ------------------ scratch (no allocations allowed) ------------------
__device__ float g_tok[BATCH*NTOK*DMODEL];
__device__ float g_resid[BL*DMODEL];
__device__ float g_hid[2][BL*DMODEL];       // split-K partials of out_proj
__device__ float g_xz[BL*2*DIN];
__device__ float g_xc[2][BL*DIN];
__device__ float g_dt[2][BL*DIN];
__device__ float g_bc[2][BL*2*NST];

// bf16 hi/lo planes for tensor-core GEMMs
__device__ __nv_bfloat16 gwp_hi[DMODEL*256],       gwp_lo[DMODEL*256];
__device__ __nv_bfloat16 gwin_hi[4*2*DIN*DMODEL],  gwin_lo[4*2*DIN*DMODEL];
__device__ __nv_bfloat16 gwout_hi[4*DMODEL*DIN],   gwout_lo[4*DMODEL*DIN];
__device__ __nv_bfloat16 ga_hi[BL*DIN],            ga_lo[BL*DIN];
__device__ __nv_bfloat16 gp_hi[BATCH*NTOK*256],    gp_lo[BATCH*NTOK*256];

__device__ __forceinline__ float4 ld4(const float* p) {
    return *reinterpret_cast<const float4*>(p);
}

// ------------------ hi/lo split helpers ------------------
__device__ __forceinline__ void split_bf16(float x, __nv_bfloat16* hi,
                                           __nv_bfloat16* lo) {
    __nv_bfloat16 h = __float2bfloat16(x);
    *hi = h;
    *lo = __float2bfloat16(x - __bfloat162float(h));
}

// ================== mma.sync GEMM machinery (base sm_103 ISA) ==================
// Tile 64x64, chunk K=64.  Buffer layout (32 KB each, double buffered):
//   A_hi [0,8K) A_lo [8K,16K) B_hi [16K,24K) B_lo [24K,32K)
#define BUFB 32768
#define SMEM_SZ (1024 + 2*BUFB)   // 66560

__device__ __forceinline__ uint32_t smem_u32(const void* p) {
    uint32_t a;
    asm("{ .reg .u64 t; cvta.to.shared.u64 t, %1; cvt.u32.u64 %0, t; }"
        : "=r"(a) : "l"(p));
    return a;
}
__device__ __forceinline__ void ldmx4(uint32_t* r, uint32_t addr) {
    asm volatile("ldmatrix.sync.aligned.m8n8.x4.shared.b16 {%0,%1,%2,%3}, [%4];"
        : "=r"(r[0]), "=r"(r[1]), "=r"(r[2]), "=r"(r[3]) : "r"(addr));
}
__device__ __forceinline__ void mma16816(float* c, const uint32_t* a,
                                         const uint32_t* b) {
    asm volatile(
        "mma.sync.aligned.m16n8k16.row.col.f32.bf16.bf16.f32 "
        "{%0,%1,%2,%3}, {%4,%5,%6,%7}, {%8,%9}, {%0,%1,%2,%3};"
        : "+f"(c[0]), "+f"(c[1]), "+f"(c[2]), "+f"(c[3])
        : "r"(a[0]), "r"(a[1]), "r"(a[2]), "r"(a[3]), "r"(b[0]), "r"(b[1]));
}
__device__ __forceinline__ void cpa16(uint32_t dst, const void* src, int nbytes) {
    asm volatile("cp.async.cg.shared.global [%0], [%1], 16, %2;"
        :: "r"(dst), "l"(src), "r"(nbytes));
}

// issue one K-chunk's loads into buffer (c & 1)
__device__ __forceinline__ void mma_issue(
    uint32_t base, int c, int tid, int m0, int n0, int koff, int M,
    const __nv_bfloat16* ah, const __nv_bfloat16* al,
    const __nv_bfloat16* wh, const __nv_bfloat16* wl, int aK, int wK)
{
    uint32_t boff = base + (c & 1) * BUFB;
    int k0 = koff + c * 64;
#pragma unroll
    for (int s = 0; s < 2; s++) {
        int idx = tid + s * 256;
        int row = idx >> 3, ch = idx & 7;
        int m = m0 + row;
        int ok = (m < M) ? 16 : 0;
        size_t moff = (size_t)(ok ? m : 0) * aK + k0 + ch * 8;
        uint32_t so = (uint32_t)(row * 128 + ch * 16);
        so ^= (so >> 3) & 0x70;
        cpa16(boff + so, ah + moff, ok);
        cpa16(boff + 8192 + so, al + moff, ok);
    }
#pragma unroll
    for (int s = 0; s < 2; s++) {
        int idx = tid + s * 256;
        int row = idx >> 3, ch = idx & 7;
        size_t noff = (size_t)(n0 + row) * wK + k0 + ch * 8;
        uint32_t so = (uint32_t)(row * 128 + ch * 16);
        so ^= (so >> 3) & 0x70;
        cpa16(boff + 16384 + so, wh + noff, 16);
        cpa16(boff + 24576 + so, wl + noff, 16);
    }
    asm volatile("cp.async.commit_group;");
}

// C[M,N] = A[M,K] * W[N,K]^T  via split-bf16 mma.sync.
// 8 warps as 4(m) x 2(n); warp tile 16 rows x 32 cols.
__global__ __launch_bounds__(256, 3)
void k_mma(const __nv_bfloat16* __restrict__ ah, const __nv_bfloat16* __restrict__ al,
           const __nv_bfloat16* __restrict__ wh, const __nv_bfloat16* __restrict__ wl,
           float* __restrict__ C, int M, int Nn, int aK, int wK, int nchunks)
{
    extern __shared__ char smraw[];
    uint32_t raw = smem_u32(smraw);
    uint32_t base = (raw + 1023) & ~1023u;
    int tid = threadIdx.x, wid = tid >> 5, lane = tid & 31;
    int m0 = blockIdx.y * 64, n0 = blockIdx.x * 64;
    int koff = blockIdx.z * nchunks * 64;
    C += (size_t)blockIdx.z * M * Nn;
    int wm = wid & 3, wn = wid >> 2;     // warp tile: rows wm*16, cols wn*32

    float acc[4][4] = {};                // [nt][frag]

    mma_issue(base, 0, tid, m0, n0, koff, M, ah, al, wh, wl, aK, wK);
    if (nchunks > 1)
        mma_issue(base, 1, tid, m0, n0, koff, M, ah, al, wh, wl, aK, wK);

    for (int c = 0; c < nchunks; c++) {
        if (c + 1 < nchunks) asm volatile("cp.async.wait_group 1;");
        else                 asm volatile("cp.async.wait_group 0;");
        __syncthreads();
        uint32_t boff = base + (c & 1) * BUFB;

#pragma unroll
        for (int ks = 0; ks < 4; ks++) {
            uint32_t a_hi[4], a_lo[4];
            {
                uint32_t row = (uint32_t)(wm * 16 + (lane & 15));
                uint32_t colb = (uint32_t)(ks * 32 + ((lane >> 4) << 4));
                uint32_t so = row * 128 + colb;
                so ^= (so >> 3) & 0x70;
                ldmx4(a_hi, boff + so);
                ldmx4(a_lo, boff + 8192 + so);
            }
            // B: one ldmx4 covers an nt pair (16 rows x 16 cols)
            uint32_t b_hi[4][2], b_lo[4][2];
#pragma unroll
            for (int pp = 0; pp < 2; pp++) {
                uint32_t row = (uint32_t)(wn * 32 + pp * 16 +
                                          ((lane >> 4) << 3) + (lane & 7));
                uint32_t colb = (uint32_t)(ks * 32 + (((lane >> 3) & 1) << 4));
                uint32_t so = row * 128 + colb;
                so ^= (so >> 3) & 0x70;
                uint32_t rh[4], rl[4];
                ldmx4(rh, boff + 16384 + so);
                ldmx4(rl, boff + 24576 + so);
                b_hi[2*pp][0] = rh[0]; b_hi[2*pp][1] = rh[1];
                b_hi[2*pp+1][0] = rh[2]; b_hi[2*pp+1][1] = rh[3];
                b_lo[2*pp][0] = rl[0]; b_lo[2*pp][1] = rl[1];
                b_lo[2*pp+1][0] = rl[2]; b_lo[2*pp+1][1] = rl[3];
            }
#pragma unroll
            for (int nt = 0; nt < 4; nt++) {
                mma16816(acc[nt], a_hi, b_hi[nt]);
                mma16816(acc[nt], a_hi, b_lo[nt]);
                mma16816(acc[nt], a_lo, b_hi[nt]);
            }
        }
        if (c + 2 < nchunks) {
            __syncthreads();   // buffer (c&1) free only after all warps consumed it
            mma_issue(base, c + 2, tid, m0, n0, koff, M, ah, al, wh, wl, aK, wK);
        }
    }

    // ---- epilogue: each warp writes its 16x32 tile ----
#pragma unroll
    for (int nt = 0; nt < 4; nt++) {
        int m = m0 + wm * 16 + (lane >> 2);
        int n = n0 + wn * 32 + nt * 8 + (lane & 3) * 2;
        if (m < M)
            *(float2*)(C + (size_t)m * Nn + n) = make_float2(acc[nt][0], acc[nt][1]);
        if (m + 8 < M)
            *(float2*)(C + (size_t)(m + 8) * Nn + n) = make_float2(acc[nt][2], acc[nt][3]);
    }
}

__device__ __forceinline__ void split4_store(float4 v, __nv_bfloat16* hp,
                                             __nv_bfloat16* lp, size_t off) {
    __nv_bfloat16 hh[4], ll[4];
    split_bf16(v.x, &hh[0], &ll[0]);
    split_bf16(v.y, &hh[1], &ll[1]);
    split_bf16(v.z, &hh[2], &ll[2]);
    split_bf16(v.w, &hh[3], &ll[3]);
    *(uint2*)(hp + off) = *(uint2*)hh;
    *(uint2*)(lp + off) = *(uint2*)ll;
}

// ------------------ merged prep: all weight splits + patch gather ------------------
#define NP0 (DMODEL*256/4)                  // patchw f4s   (24576)
#define NP1 (4*2*DIN*DMODEL/4)              // inpw f4s     (589824)
#define NP2 (4*DMODEL*DIN/4)                // outw f4s     (294912)
#define NP3 (BATCH*NTOK*256/4)              // patch gather (65536)
__global__ void k_prep(const float* __restrict__ patchw,
                       const float* __restrict__ inpw,
                       const float* __restrict__ outw,
                       const float* __restrict__ depth) {
    const int total = NP0 + NP1 + NP2 + NP3;
    for (int i = blockIdx.x * 256 + threadIdx.x; i < total; i += gridDim.x * 256) {
        if (i < NP0) {
            split4_store(ld4(patchw + (size_t)i * 4), gwp_hi, gwp_lo, (size_t)i * 4);
        } else if (i < NP0 + NP1) {
            size_t j = i - NP0;
            split4_store(ld4(inpw + j * 4), gwin_hi, gwin_lo, j * 4);
        } else if (i < NP0 + NP1 + NP2) {
            size_t j = i - NP0 - NP1;
            split4_store(ld4(outw + j * 4), gwout_hi, gwout_lo, j * 4);
        } else {
            int j = i - NP0 - NP1 - NP2;
            int m = j >> 6, k = (j & 63) * 4;       // row m of 256 cols, col k
            int b = m >> 8, p = m & 255;
            int ii = k >> 4, jj = k & 15;
            int gh = p >> 3, gw = p & 7;
            int row = gh * 16 + ii;
            int tt = row >> 7, hh = row & 127;
            int col = gw * 16 + jj;
            float4 v = ld4(depth + (size_t)(((b * 4 + tt) << 7) + hh) * 128 + col);
            split4_store(v, gp_hi, gp_lo, (size_t)m * 256 + k);
        }
    }
}

// ------------------ residual/assemble + LN -> split bf16 A (K=384) ------------------
// mode 0: assemble from tok/cls/pos (layer 0).  mode 1: add split-K partials.
__global__ void k_lnadd(int mode, const float* __restrict__ w,
                        const float* __restrict__ bb,
                        const float* __restrict__ cls,
                        const float* __restrict__ pos,
                        const float* __restrict__ pb) {
    int row = blockIdx.x * 8 + (threadIdx.x >> 5);
    int lane = threadIdx.x & 31;
    if (row >= BL) return;
    float* rp = g_resid + (size_t)row * DMODEL;
    float v[12];
    float s = 0.f;
    if (mode == 0) {
        int b = row / LQ, l = row - b * LQ;
#pragma unroll
        for (int q = 0; q < 12; q++) {
            int d = lane + 32 * q;
            float x;
            if (l == POSI) x = cls[d];
            else {
                int p = (l < POSI) ? l : (l - 1);
                x = g_tok[(size_t)(b * NTOK + p) * DMODEL + d] + pb[d];
            }
            x += pos[l * DMODEL + d];
            rp[d] = x;
            v[q] = x; s += x;
        }
    } else {
        const float* h0 = g_hid[0] + (size_t)row * DMODEL;
        const float* h1 = g_hid[1] + (size_t)row * DMODEL;
#pragma unroll
        for (int q = 0; q < 12; q++) {
            int d = lane + 32 * q;
            float x = rp[d] + h0[d] + h1[d];
            rp[d] = x;
            v[q] = x; s += x;
        }
    }
#pragma unroll
    for (int m = 16; m; m >>= 1) s += __shfl_xor_sync(0xffffffffu, s, m);
    float mean = s * (1.f / DMODEL);
    float sq = 0.f;
#pragma unroll
    for (int q = 0; q < 12; q++) { float dv = v[q] - mean; sq += dv * dv; }
#pragma unroll
    for (int m = 16; m; m >>= 1) sq += __shfl_xor_sync(0xffffffffu, sq, m);
    float rstd = rsqrtf(sq * (1.f / DMODEL) + 1e-5f);
#pragma unroll
    for (int q = 0; q < 12; q++) {
        int d = lane + 32 * q;
        float y = (v[q] - mean) * rstd * w[d] + bb[d];
        split_bf16(y, &ga_hi[(size_t)row * DMODEL + d],
                      &ga_lo[(size_t)row * DMODEL + d]);
    }
}

// ------------------ fused conv+silu -> xproj -> B,C -> dtproj+softplus ------------------
__global__ void k_xproj(const float* __restrict__ cwf, const float* __restrict__ cbf,
                        const float* __restrict__ cwb, const float* __restrict__ cbb,
                        const float* __restrict__ xwf, const float* __restrict__ xwb,
                        const float* __restrict__ dwf, const float* __restrict__ dbf,
                        const float* __restrict__ dwb, const float* __restrict__ dbb) {
    __shared__ __align__(16) float sxc[XR][DIN];
    __shared__ float sdb[XR * 56];
    int l0 = blockIdx.x * XR;
    int b = blockIdx.y, br = blockIdx.z;
    int tid = threadIdx.x;                 // 256
    const float* cw = br ? cwb : cwf;
    const float* cb = br ? cbb : cbf;

    // phase 0: conv + silu, sliding window over rows (each row loaded once)
    for (int d = tid; d < DIN; d += 256) {
        float4 wc = ld4(&cw[d * KCONV]);
        float wct[4] = {wc.x, wc.y, wc.z, wc.w};
        float bias = cb[d];
        float v[XR + 3];
#pragma unroll
        for (int j = 0; j < XR + 3; j++) {
            int idx = l0 - 3 + j;
            float x = 0.f;
            if (idx >= 0 && idx <= NTOK) {
                int src = br ? (NTOK - idx) : idx;
                x = g_xz[(size_t)(b * LQ + src) * (2 * DIN) + d];
            }
            v[j] = x;
        }
#pragma unroll
        for (int r = 0; r < XR; r++) {
            int l = l0 + r;
            float val = 0.f;
            if (l < LQ) {
                float acc = bias + wct[0] * v[r] + wct[1] * v[r + 1] +
                            wct[2] * v[r + 2] + wct[3] * v[r + 3];
                val = acc / (1.f + __expf(-acc));
                g_xc[br][(size_t)(b * LQ + l) * DIN + d] = val;
            }
            sxc[r][d] = val;
        }
    }
    __syncthreads();

    {
        const float* xw = br ? xwb : xwf;
        int wid = tid >> 5, lane = tid & 31;
        for (int e = wid; e < 56; e += 8) {
            float4 w4[6];
#pragma unroll
            for (int j = 0; j < 6; j++)
                w4[j] = ld4(&xw[(size_t)e * DIN + lane * 4 + 128 * j]);
#pragma unroll
            for (int r = 0; r < XR; r++) {
                float p = 0.f;
#pragma unroll
                for (int j = 0; j < 6; j++) {
                    float4 s4 = ld4(&sxc[r][lane * 4 + 128 * j]);
                    p += w4[j].x * s4.x + w4[j].y * s4.y +
                         w4[j].z * s4.z + w4[j].w * s4.w;
                }
#pragma unroll
                for (int m = 16; m; m >>= 1) p += __shfl_xor_sync(0xffffffffu, p, m);
                if (lane == 0) sdb[r * 56 + e] = p;
            }
        }
    }
    __syncthreads();

    {
        int r = tid >> 5, n = tid & 31;       // XR*32 = 256 threads exactly
        int l = l0 + r;
        if (l < LQ) g_bc[br][(size_t)(b * LQ + l) * 32 + n] = sdb[r * 56 + 24 + n];
    }

    const float* dw = br ? dwb : dwf;
    const float* db = br ? dbb : dbf;
    for (int d = tid; d < DIN; d += 256) {
        float4 w4[6];
#pragma unroll
        for (int j = 0; j < 6; j++) w4[j] = ld4(&dw[(size_t)d * DTR + j * 4]);
        float bias = db[d];
#pragma unroll
        for (int r = 0; r < XR; r++) {
            int l = l0 + r;
            if (l >= LQ) break;
            const float* sp = &sdb[r * 56];
            float acc = bias;
#pragma unroll
            for (int j = 0; j < 6; j++) {
                acc += w4[j].x * sp[j * 4 + 0] + w4[j].y * sp[j * 4 + 1] +
                       w4[j].z * sp[j * 4 + 2] + w4[j].w * sp[j * 4 + 3];
            }
            float spv = (acc > 20.f) ? acc : log1pf(__expf(acc));
            g_dt[br][(size_t)(b * LQ + l) * DIN + d] = spv;
        }
    }
}

// ------------------ dual-branch selective scan + combine + gate + split ------------------
// Block (chunk, b), 512 threads: lower 256 = forward branch, upper 256 = backward.
// Scans write y into smem; epilogue combines yf[l]+yb[NTOK-l], applies silu(z),
// splits to ga_hi/ga_lo (A of out_proj).  No g_y global round-trip.
#define SSM_SMEM (2*LQ*32*4 + 2*LQ*16*4)   // 65792 + 32896 = 98688
__global__ __launch_bounds__(512)
void k_ssm(const float* __restrict__ Alf, const float* __restrict__ Alb,
           const float* __restrict__ Dpf, const float* __restrict__ Dpb) {
    extern __shared__ float sm[];
    float* sBC = sm;                     // [2][LQ][32]
    float* sy  = sm + 2 * LQ * 32;       // [2][LQ][16]
    int chunk = blockIdx.x, b = blockIdx.y;
    int tid = threadIdx.x;
    int br = tid >> 8;
    int t256 = tid & 255;
    int n = t256 & 15, dl = t256 >> 4;
    int d = chunk * 16 + dl;

    // load both branches' B/C
    {
        const float4* src0 = (const float4*)(g_bc[0] + (size_t)b * LQ * 32);
        const float4* src1 = (const float4*)(g_bc[1] + (size_t)b * LQ * 32);
        float4* dst = (float4*)sBC;
        for (int i = tid; i < LQ * 8; i += 512) {
            dst[i] = src0[i];
            dst[LQ * 8 + i] = src1[i];
        }
    }
    const float* Al = br ? Alb : Alf;
    float A = -__expf(Al[(size_t)d * NST + n]);
    float Dv = (br ? Dpb : Dpf)[d];
    const float* dtp = g_dt[br] + (size_t)b * LQ * DIN + d;
    const float* xcp = g_xc[br] + (size_t)b * LQ * DIN + d;
    float* syb = sy + br * LQ * 16;
    const float* bcb = sBC + br * LQ * 32;
    __syncthreads();

    float h = 0.f;
    float dt0 = dtp[0], xc0 = xcp[0];
    float dt1 = dtp[DIN], xc1 = xcp[DIN];
    for (int t = 0; t < LQ; t++) {
        float dtv = dt0, xv = xc0;
        dt0 = dt1; xc0 = xc1;
        int tp = (t + 2 < LQ) ? t + 2 : LQ - 1;
        dt1 = dtp[(size_t)tp * DIN];
        xc1 = xcp[(size_t)tp * DIN];
        float dA = __expf(dtv * A);
        h = dA * h + dtv * bcb[t * 32 + n] * xv;
        float p = h * bcb[t * 32 + 16 + n];
        p += __shfl_xor_sync(0xffffffffu, p, 8);
        p += __shfl_xor_sync(0xffffffffu, p, 4);
        p += __shfl_xor_sync(0xffffffffu, p, 2);
        p += __shfl_xor_sync(0xffffffffu, p, 1);
        if (n == 0) syb[t * 16 + dl] = p + xv * Dv;
    }
    __syncthreads();

    // epilogue: combine + silu(z) gate + hi/lo split -> ga planes
    for (int i = tid; i < LQ * 16; i += 512) {
        int t = i >> 4, dd = i & 15;
        int gd = chunk * 16 + dd;
        float z = g_xz[(size_t)(b * LQ + t) * (2 * DIN) + DIN + gd];
        float comb = (sy[t * 16 + dd] + sy[LQ * 16 + (NTOK - t) * 16 + dd]) *
                     (z / (1.f + __expf(-z)));
        split_bf16(comb, &ga_hi[(size_t)(b * LQ + t) * DIN + gd],
                         &ga_lo[(size_t)(b * LQ + t) * DIN + gd]);
    }
}

// ------------------ final residual + LN + cmd MLP head ------------------
__global__ void k_final(const float* __restrict__ sv, const float* __restrict__ av,
                        const float* __restrict__ lnw, const float* __restrict__ lnb,
                        const float* __restrict__ cw1, const float* __restrict__ cb1,
                        const float* __restrict__ cw2, const float* __restrict__ cb2,
                        float* __restrict__ out) {
    int b = blockIdx.x, tid = threadIdx.x;   // 384 threads
    __shared__ float c1[DMODEL], svis[DMODEL], cmdv[20], red[12];
    int row = b * LQ + POSI;
    float x = g_resid[(size_t)row * DMODEL + tid] +
              g_hid[0][(size_t)row * DMODEL + tid] +
              g_hid[1][(size_t)row * DMODEL + tid];
    float s = x;
#pragma unroll
    for (int m = 16; m; m >>= 1) s += __shfl_xor_sync(0xffffffffu, s, m);
    if ((tid & 31) == 0) red[tid >> 5] = s;
    __syncthreads();
    float tot = 0.f;
#pragma unroll
    for (int i = 0; i < 12; i++) tot += red[i];
    float mean = tot * (1.0f / DMODEL);
    float dv = x - mean;
    float vsq = dv * dv;
    __syncthreads();
#pragma unroll
    for (int m = 16; m; m >>= 1) vsq += __shfl_xor_sync(0xffffffffu, vsq, m);
    if ((tid & 31) == 0) red[tid >> 5] = vsq;
    __syncthreads();
    float vt = 0.f;
#pragma unroll
    for (int i = 0; i < 12; i++) vt += red[i];
    svis[tid] = dv * rsqrtf(vt * (1.0f / DMODEL) + 1e-5f) * lnw[tid] + lnb[tid];
    if (tid < 20) cmdv[tid] = (tid < 16) ? sv[b * 16 + tid] : av[b * 4 + tid - 16];
    __syncthreads();
    float a1 = cb1[tid];
#pragma unroll
    for (int k = 0; k < 20; k++) a1 += cmdv[k] * cw1[tid * 20 + k];
    c1[tid] = fmaxf(a1, 0.f);
    __syncthreads();
    int w = tid >> 5, lane = tid & 31;
    for (int r = w; r < DMODEL; r += 12) {
        float p = 0.f;
        const float* wr = cw2 + (size_t)r * DMODEL;
#pragma unroll
        for (int j = 0; j < 12; j++) p += c1[lane + 32 * j] * wr[lane + 32 * j];
#pragma unroll
        for (int m = 16; m; m >>= 1) p += __shfl_xor_sync(0xffffffffu, p, m);
        if (lane == 0) out[b * DMODEL + r] = svis[r] + p + cb2[r];
    }
}

// ------------------ host ------------------
extern "C" void kernel_launch(void* const* d_in, const int* in_sizes, int n_in,
                              void* d_out, int out_size) {
    const float* depth  = (const float*)d_in[0];
    const float* state  = (const float*)d_in[1];
    const float* action = (const float*)d_in[2];
    const float* patchw = (const float*)d_in[3];
    const float* patchb = (const float*)d_in[4];
    const float* cls    = (const float*)d_in[5];
    const float* pos    = (const float*)d_in[6];
    const float* lnw    = (const float*)d_in[7];
    const float* lnb    = (const float*)d_in[8];
    const float* inpw   = (const float*)d_in[9];
    const float* convw  = (const float*)d_in[10];
    const float* convb  = (const float*)d_in[11];
    const float* convwb = (const float*)d_in[12];
    const float* convbb = (const float*)d_in[13];
    const float* xpw    = (const float*)d_in[14];
    const float* xpwb   = (const float*)d_in[15];
    const float* dtw    = (const float*)d_in[16];
    const float* dtbv   = (const float*)d_in[17];
    const float* dtwb   = (const float*)d_in[18];
    const float* dtbb   = (const float*)d_in[19];
    const float* Alog   = (const float*)d_in[20];
    const float* Alogb  = (const float*)d_in[21];
    const float* Dp     = (const float*)d_in[22];
    const float* Dpb    = (const float*)d_in[23];
    const float* outw   = (const float*)d_in[24];
    const float* lnfw   = (const float*)d_in[25];
    const float* lnfb   = (const float*)d_in[26];
    const float* cw1    = (const float*)d_in[27];
    const float* cb1    = (const float*)d_in[28];
    const float* cw2    = (const float*)d_in[29];
    const float* cb2    = (const float*)d_in[30];

    float *p_tok, *p_xz, *p_hid;
    __nv_bfloat16 *p_wp_hi, *p_wp_lo, *p_win_hi, *p_win_lo, *p_wout_hi, *p_wout_lo;
    __nv_bfloat16 *p_a_hi, *p_a_lo, *p_p_hi, *p_p_lo;
    cudaGetSymbolAddress((void**)&p_tok, g_tok);
    cudaGetSymbolAddress((void**)&p_xz, g_xz);
    cudaGetSymbolAddress((void**)&p_hid, g_hid);
    cudaGetSymbolAddress((void**)&p_wp_hi, gwp_hi);
    cudaGetSymbolAddress((void**)&p_wp_lo, gwp_lo);
    cudaGetSymbolAddress((void**)&p_win_hi, gwin_hi);
    cudaGetSymbolAddress((void**)&p_win_lo, gwin_lo);
    cudaGetSymbolAddress((void**)&p_wout_hi, gwout_hi);
    cudaGetSymbolAddress((void**)&p_wout_lo, gwout_lo);
    cudaGetSymbolAddress((void**)&p_a_hi, ga_hi);
    cudaGetSymbolAddress((void**)&p_a_lo, ga_lo);
    cudaGetSymbolAddress((void**)&p_p_hi, gp_hi);
    cudaGetSymbolAddress((void**)&p_p_lo, gp_lo);

    cudaFuncSetAttribute(k_mma, cudaFuncAttributeMaxDynamicSharedMemorySize, SMEM_SZ);
    cudaFuncSetAttribute(k_ssm, cudaFuncAttributeMaxDynamicSharedMemorySize, SSM_SMEM);

    // merged prep: weight splits + patch gather (1 launch)
    k_prep<<<1024, 256>>>(patchw, inpw, outw, depth);

    // patch embed: M=1024, N=384, K=256
    k_mma<<<dim3(6, 16, 1), 256, SMEM_SZ>>>(p_p_hi, p_p_lo, p_wp_hi, p_wp_lo,
                                            p_tok, BATCH * NTOK, DMODEL, 256, 256, 4);

    for (int i = 0; i < 4; i++) {
        // layer 0: assemble (tok+cls+pos) fused into lnadd mode 0
        k_lnadd<<<(BL + 7) / 8, 256>>>(i == 0 ? 0 : 1,
                                       lnw + i * DMODEL, lnb + i * DMODEL,
                                       cls, pos, patchb);
        // in_proj: M=1028, N=1536, K=384
        k_mma<<<dim3(24, 17, 1), 256, SMEM_SZ>>>(
            p_a_hi, p_a_lo,
            p_win_hi + (size_t)i * 2 * DIN * DMODEL,
            p_win_lo + (size_t)i * 2 * DIN * DMODEL,
            p_xz, BL, 2 * DIN, DMODEL, DMODEL, 6);
        k_xproj<<<dim3((LQ + XR - 1) / XR, BATCH, 2), 256>>>(
            convw + i * DIN * KCONV, convb + i * DIN,
            convwb + i * DIN * KCONV, convbb + i * DIN,
            xpw + (size_t)i * 56 * DIN, xpwb + (size_t)i * 56 * DIN,
            dtw + (size_t)i * DIN * DTR, dtbv + i * DIN,
            dtwb + (size_t)i * DIN * DTR, dtbb + i * DIN);
        // dual-branch scan + combine + gate + split (prepA1 fused)
        k_ssm<<<dim3(DIN / 16, BATCH), 512, SSM_SMEM>>>(
            Alog + (size_t)i * DIN * NST, Alogb + (size_t)i * DIN * NST,
            Dp + i * DIN, Dpb + i * DIN);
        // out_proj: M=1028, N=384, K=768, split-K=2 via blockIdx.z
        k_mma<<<dim3(6, 17, 2), 256, SMEM_SZ>>>(
            p_a_hi, p_a_lo,
            p_wout_hi + (size_t)i * DMODEL * DIN,
            p_wout_lo + (size_t)i * DMODEL * DIN,
            p_hid, BL, DMODEL, DIN, DIN, 6);
    }

    k_final<<<BATCH, DMODEL>>>(state, action, lnfw, lnfb, cw1, cb1, cw2, cb2,
                               (float*)d_out);
}

// round 15
// speedup vs baseline: 1.4379x; 1.4379x over previous
#include <cuda_runtime.h>
#include <cuda_bf16.h>
#include <cstdint>
#include <math.h>

#define BATCH 4
#define LQ 257        // NTOK+1
#define DMODEL 384
#define DIN 768
#define NST 16
#define DTR 24
#define KCONV 4
#define NTOK 256
#define POSI 128
#define BL (BATCH*LQ)   // 1028
#define XR 8            // xproj row tile

// ------------------ scratch (no allocations allowed) ------------------
__device__ float g_tok[BATCH*NTOK*DMODEL];
__device__ float g_resid[BL*DMODEL];
__device__ float g_hid[2][BL*DMODEL];       // split-K partials of out_proj
__device__ float g_xz[BL*2*DIN];
__device__ float g_xc[2][BL*DIN];
__device__ float g_dt[2][BL*DIN];
__device__ float g_bc[2][BL*2*NST];
__device__ float g_y[2][BL*DIN];

// bf16 hi/lo planes for tensor-core GEMMs
__device__ __nv_bfloat16 gwp_hi[DMODEL*256],       gwp_lo[DMODEL*256];
__device__ __nv_bfloat16 gwin_hi[4*2*DIN*DMODEL],  gwin_lo[4*2*DIN*DMODEL];
__device__ __nv_bfloat16 gwout_hi[4*DMODEL*DIN],   gwout_lo[4*DMODEL*DIN];
__device__ __nv_bfloat16 ga_hi[BL*DIN],            ga_lo[BL*DIN];
__device__ __nv_bfloat16 gp_hi[BATCH*NTOK*256],    gp_lo[BATCH*NTOK*256];

__device__ __forceinline__ float4 ld4(const float* p) {
    return *reinterpret_cast<const float4*>(p);
}

// ------------------ hi/lo split helpers ------------------
__device__ __forceinline__ void split_bf16(float x, __nv_bfloat16* hi,
                                           __nv_bfloat16* lo) {
    __nv_bfloat16 h = __float2bfloat16(x);
    *hi = h;
    *lo = __float2bfloat16(x - __bfloat162float(h));
}

// ================== mma.sync GEMM machinery (base sm_103 ISA) ==================
// Tile 64x64, chunk K=64.  Buffer layout (32 KB each, double buffered):
//   A_hi [0,8K) A_lo [8K,16K) B_hi [16K,24K) B_lo [24K,32K)
#define BUFB 32768
#define SMEM_SZ (1024 + 2*BUFB)   // 66560

__device__ __forceinline__ uint32_t smem_u32(const void* p) {
    uint32_t a;
    asm("{ .reg .u64 t; cvta.to.shared.u64 t, %1; cvt.u32.u64 %0, t; }"
        : "=r"(a) : "l"(p));
    return a;
}
__device__ __forceinline__ void ldmx4(uint32_t* r, uint32_t addr) {
    asm volatile("ldmatrix.sync.aligned.m8n8.x4.shared.b16 {%0,%1,%2,%3}, [%4];"
        : "=r"(r[0]), "=r"(r[1]), "=r"(r[2]), "=r"(r[3]) : "r"(addr));
}
__device__ __forceinline__ void mma16816(float* c, const uint32_t* a,
                                         const uint32_t* b) {
    asm volatile(
        "mma.sync.aligned.m16n8k16.row.col.f32.bf16.bf16.f32 "
        "{%0,%1,%2,%3}, {%4,%5,%6,%7}, {%8,%9}, {%0,%1,%2,%3};"
        : "+f"(c[0]), "+f"(c[1]), "+f"(c[2]), "+f"(c[3])
        : "r"(a[0]), "r"(a[1]), "r"(a[2]), "r"(a[3]), "r"(b[0]), "r"(b[1]));
}
// .ca: cache in L1 too — co-resident CTAs re-read the same W/A tiles
__device__ __forceinline__ void cpa16(uint32_t dst, const void* src, int nbytes) {
    asm volatile("cp.async.ca.shared.global [%0], [%1], 16, %2;"
        :: "r"(dst), "l"(src), "r"(nbytes));
}

// issue one K-chunk's loads into buffer (c & 1)
__device__ __forceinline__ void mma_issue(
    uint32_t base, int c, int tid, int m0, int n0, int koff, int M,
    const __nv_bfloat16* ah, const __nv_bfloat16* al,
    const __nv_bfloat16* wh, const __nv_bfloat16* wl, int aK, int wK)
{
    uint32_t boff = base + (c & 1) * BUFB;
    int k0 = koff + c * 64;
#pragma unroll
    for (int s = 0; s < 2; s++) {
        int idx = tid + s * 256;
        int row = idx >> 3, ch = idx & 7;
        int m = m0 + row;
        int ok = (m < M) ? 16 : 0;
        size_t moff = (size_t)(ok ? m : 0) * aK + k0 + ch * 8;
        uint32_t so = (uint32_t)(row * 128 + ch * 16);
        so ^= (so >> 3) & 0x70;
        cpa16(boff + so, ah + moff, ok);
        cpa16(boff + 8192 + so, al + moff, ok);
    }
#pragma unroll
    for (int s = 0; s < 2; s++) {
        int idx = tid + s * 256;
        int row = idx >> 3, ch = idx & 7;
        size_t noff = (size_t)(n0 + row) * wK + k0 + ch * 8;
        uint32_t so = (uint32_t)(row * 128 + ch * 16);
        so ^= (so >> 3) & 0x70;
        cpa16(boff + 16384 + so, wh + noff, 16);
        cpa16(boff + 24576 + so, wl + noff, 16);
    }
    asm volatile("cp.async.commit_group;");
}

// C[M,N] = A[M,K] * W[N,K]^T  via split-bf16 mma.sync.
// 8 warps as 4(m) x 2(n); warp tile 16 rows x 32 cols.
__global__ __launch_bounds__(256, 3)
void k_mma(const __nv_bfloat16* __restrict__ ah, const __nv_bfloat16* __restrict__ al,
           const __nv_bfloat16* __restrict__ wh, const __nv_bfloat16* __restrict__ wl,
           float* __restrict__ C, int M, int Nn, int aK, int wK, int nchunks)
{
    extern __shared__ char smraw[];
    uint32_t raw = smem_u32(smraw);
    uint32_t base = (raw + 1023) & ~1023u;
    int tid = threadIdx.x, wid = tid >> 5, lane = tid & 31;
    int m0 = blockIdx.y * 64, n0 = blockIdx.x * 64;
    int koff = blockIdx.z * nchunks * 64;
    C += (size_t)blockIdx.z * M * Nn;
    int wm = wid & 3, wn = wid >> 2;     // warp tile: rows wm*16, cols wn*32

    float acc[4][4] = {};                // [nt][frag]

    mma_issue(base, 0, tid, m0, n0, koff, M, ah, al, wh, wl, aK, wK);
    if (nchunks > 1)
        mma_issue(base, 1, tid, m0, n0, koff, M, ah, al, wh, wl, aK, wK);

    for (int c = 0; c < nchunks; c++) {
        if (c + 1 < nchunks) asm volatile("cp.async.wait_group 1;");
        else                 asm volatile("cp.async.wait_group 0;");
        __syncthreads();
        uint32_t boff = base + (c & 1) * BUFB;

#pragma unroll
        for (int ks = 0; ks < 4; ks++) {
            uint32_t a_hi[4], a_lo[4];
            {
                uint32_t row = (uint32_t)(wm * 16 + (lane & 15));
                uint32_t colb = (uint32_t)(ks * 32 + ((lane >> 4) << 4));
                uint32_t so = row * 128 + colb;
                so ^= (so >> 3) & 0x70;
                ldmx4(a_hi, boff + so);
                ldmx4(a_lo, boff + 8192 + so);
            }
            // B: one ldmx4 covers an nt pair (16 rows x 16 cols)
            uint32_t b_hi[4][2], b_lo[4][2];
#pragma unroll
            for (int pp = 0; pp < 2; pp++) {
                uint32_t row = (uint32_t)(wn * 32 + pp * 16 +
                                          ((lane >> 4) << 3) + (lane & 7));
                uint32_t colb = (uint32_t)(ks * 32 + (((lane >> 3) & 1) << 4));
                uint32_t so = row * 128 + colb;
                so ^= (so >> 3) & 0x70;
                uint32_t rh[4], rl[4];
                ldmx4(rh, boff + 16384 + so);
                ldmx4(rl, boff + 24576 + so);
                b_hi[2*pp][0] = rh[0]; b_hi[2*pp][1] = rh[1];
                b_hi[2*pp+1][0] = rh[2]; b_hi[2*pp+1][1] = rh[3];
                b_lo[2*pp][0] = rl[0]; b_lo[2*pp][1] = rl[1];
                b_lo[2*pp+1][0] = rl[2]; b_lo[2*pp+1][1] = rl[3];
            }
#pragma unroll
            for (int nt = 0; nt < 4; nt++) {
                mma16816(acc[nt], a_hi, b_hi[nt]);
                mma16816(acc[nt], a_hi, b_lo[nt]);
                mma16816(acc[nt], a_lo, b_hi[nt]);
            }
        }
        if (c + 2 < nchunks) {
            __syncthreads();   // buffer (c&1) free only after all warps consumed it
            mma_issue(base, c + 2, tid, m0, n0, koff, M, ah, al, wh, wl, aK, wK);
        }
    }

    // ---- epilogue: each warp writes its 16x32 tile ----
#pragma unroll
    for (int nt = 0; nt < 4; nt++) {
        int m = m0 + wm * 16 + (lane >> 2);
        int n = n0 + wn * 32 + nt * 8 + (lane & 3) * 2;
        if (m < M)
            *(float2*)(C + (size_t)m * Nn + n) = make_float2(acc[nt][0], acc[nt][1]);
        if (m + 8 < M)
            *(float2*)(C + (size_t)(m + 8) * Nn + n) = make_float2(acc[nt][2], acc[nt][3]);
    }
}

__device__ __forceinline__ void split4_store(float4 v, __nv_bfloat16* hp,
                                             __nv_bfloat16* lp, size_t off) {
    __nv_bfloat16 hh[4], ll[4];
    split_bf16(v.x, &hh[0], &ll[0]);
    split_bf16(v.y, &hh[1], &ll[1]);
    split_bf16(v.z, &hh[2], &ll[2]);
    split_bf16(v.w, &hh[3], &ll[3]);
    *(uint2*)(hp + off) = *(uint2*)hh;
    *(uint2*)(lp + off) = *(uint2*)ll;
}

// ------------------ merged prep: all weight splits + patch gather ------------------
#define NP0 (DMODEL*256/4)                  // patchw f4s   (24576)
#define NP1 (4*2*DIN*DMODEL/4)              // inpw f4s     (589824)
#define NP2 (4*DMODEL*DIN/4)                // outw f4s     (294912)
#define NP3 (BATCH*NTOK*256/4)              // patch gather (65536)
__global__ void k_prep(const float* __restrict__ patchw,
                       const float* __restrict__ inpw,
                       const float* __restrict__ outw,
                       const float* __restrict__ depth) {
    const int total = NP0 + NP1 + NP2 + NP3;
    for (int i = blockIdx.x * 256 + threadIdx.x; i < total; i += gridDim.x * 256) {
        if (i < NP0) {
            split4_store(ld4(patchw + (size_t)i * 4), gwp_hi, gwp_lo, (size_t)i * 4);
        } else if (i < NP0 + NP1) {
            size_t j = i - NP0;
            split4_store(ld4(inpw + j * 4), gwin_hi, gwin_lo, j * 4);
        } else if (i < NP0 + NP1 + NP2) {
            size_t j = i - NP0 - NP1;
            split4_store(ld4(outw + j * 4), gwout_hi, gwout_lo, j * 4);
        } else {
            int j = i - NP0 - NP1 - NP2;
            int m = j >> 6, k = (j & 63) * 4;       // row m of 256 cols, col k
            int b = m >> 8, p = m & 255;
            int ii = k >> 4, jj = k & 15;
            int gh = p >> 3, gw = p & 7;
            int row = gh * 16 + ii;
            int tt = row >> 7, hh = row & 127;
            int col = gw * 16 + jj;
            float4 v = ld4(depth + (size_t)(((b * 4 + tt) << 7) + hh) * 128 + col);
            split4_store(v, gp_hi, gp_lo, (size_t)m * 256 + k);
        }
    }
}

// combine + silu(z) gate + split  (A of out_proj, K=768), float4
__global__ void k_prepA1() {
    int m = blockIdx.x;                       // BL blocks x 192 threads
    int b = m / LQ, l = m - b * LQ;
    const float* yf = g_y[0] + (size_t)m * DIN;
    const float* yb = g_y[1] + (size_t)(b * LQ + (NTOK - l)) * DIN;
    const float* zp = g_xz + (size_t)m * (2 * DIN) + DIN;
    int k = threadIdx.x * 4;
    float4 z = ld4(zp + k), u = ld4(yf + k), v = ld4(yb + k);
    float4 x;
    x.x = (u.x + v.x) * (z.x / (1.f + __expf(-z.x)));
    x.y = (u.y + v.y) * (z.y / (1.f + __expf(-z.y)));
    x.z = (u.z + v.z) * (z.z / (1.f + __expf(-z.z)));
    x.w = (u.w + v.w) * (z.w / (1.f + __expf(-z.w)));
    split4_store(x, ga_hi, ga_lo, (size_t)m * DIN + k);
}

// ------------------ residual/assemble + LN -> split bf16 A (K=384) ------------------
// mode 0: assemble from tok/cls/pos (layer 0).  mode 1: add split-K partials.
__global__ void k_lnadd(int mode, const float* __restrict__ w,
                        const float* __restrict__ bb,
                        const float* __restrict__ cls,
                        const float* __restrict__ pos,
                        const float* __restrict__ pb) {
    int row = blockIdx.x * 8 + (threadIdx.x >> 5);
    int lane = threadIdx.x & 31;
    if (row >= BL) return;
    float* rp = g_resid + (size_t)row * DMODEL;
    float v[12];
    float s = 0.f;
    if (mode == 0) {
        int b = row / LQ, l = row - b * LQ;
#pragma unroll
        for (int q = 0; q < 12; q++) {
            int d = lane + 32 * q;
            float x;
            if (l == POSI) x = cls[d];
            else {
                int p = (l < POSI) ? l : (l - 1);
                x = g_tok[(size_t)(b * NTOK + p) * DMODEL + d] + pb[d];
            }
            x += pos[l * DMODEL + d];
            rp[d] = x;
            v[q] = x; s += x;
        }
    } else {
        const float* h0 = g_hid[0] + (size_t)row * DMODEL;
        const float* h1 = g_hid[1] + (size_t)row * DMODEL;
#pragma unroll
        for (int q = 0; q < 12; q++) {
            int d = lane + 32 * q;
            float x = rp[d] + h0[d] + h1[d];
            rp[d] = x;
            v[q] = x; s += x;
        }
    }
#pragma unroll
    for (int m = 16; m; m >>= 1) s += __shfl_xor_sync(0xffffffffu, s, m);
    float mean = s * (1.f / DMODEL);
    float sq = 0.f;
#pragma unroll
    for (int q = 0; q < 12; q++) { float dv = v[q] - mean; sq += dv * dv; }
#pragma unroll
    for (int m = 16; m; m >>= 1) sq += __shfl_xor_sync(0xffffffffu, sq, m);
    float rstd = rsqrtf(sq * (1.f / DMODEL) + 1e-5f);
#pragma unroll
    for (int q = 0; q < 12; q++) {
        int d = lane + 32 * q;
        float y = (v[q] - mean) * rstd * w[d] + bb[d];
        split_bf16(y, &ga_hi[(size_t)row * DMODEL + d],
                      &ga_lo[(size_t)row * DMODEL + d]);
    }
}

// ------------------ fused conv+silu -> xproj -> B,C -> dtproj+softplus ------------------
__global__ void k_xproj(const float* __restrict__ cwf, const float* __restrict__ cbf,
                        const float* __restrict__ cwb, const float* __restrict__ cbb,
                        const float* __restrict__ xwf, const float* __restrict__ xwb,
                        const float* __restrict__ dwf, const float* __restrict__ dbf,
                        const float* __restrict__ dwb, const float* __restrict__ dbb) {
    __shared__ __align__(16) float sxc[XR][DIN];
    __shared__ float sdb[XR * 56];
    int l0 = blockIdx.x * XR;
    int b = blockIdx.y, br = blockIdx.z;
    int tid = threadIdx.x;                 // 256
    const float* cw = br ? cwb : cwf;
    const float* cb = br ? cbb : cbf;

    // phase 0: conv + silu, sliding window over rows (each row loaded once)
    for (int d = tid; d < DIN; d += 256) {
        float4 wc = ld4(&cw[d * KCONV]);
        float wct[4] = {wc.x, wc.y, wc.z, wc.w};
        float bias = cb[d];
        float v[XR + 3];
#pragma unroll
        for (int j = 0; j < XR + 3; j++) {
            int idx = l0 - 3 + j;
            float x = 0.f;
            if (idx >= 0 && idx <= NTOK) {
                int src = br ? (NTOK - idx) : idx;
                x = g_xz[(size_t)(b * LQ + src) * (2 * DIN) + d];
            }
            v[j] = x;
        }
#pragma unroll
        for (int r = 0; r < XR; r++) {
            int l = l0 + r;
            float val = 0.f;
            if (l < LQ) {
                float acc = bias + wct[0] * v[r] + wct[1] * v[r + 1] +
                            wct[2] * v[r + 2] + wct[3] * v[r + 3];
                val = acc / (1.f + __expf(-acc));
                g_xc[br][(size_t)(b * LQ + l) * DIN + d] = val;
            }
            sxc[r][d] = val;
        }
    }
    __syncthreads();

    {
        const float* xw = br ? xwb : xwf;
        int wid = tid >> 5, lane = tid & 31;
        for (int e = wid; e < 56; e += 8) {
            float4 w4[6];
#pragma unroll
            for (int j = 0; j < 6; j++)
                w4[j] = ld4(&xw[(size_t)e * DIN + lane * 4 + 128 * j]);
#pragma unroll
            for (int r = 0; r < XR; r++) {
                float p = 0.f;
#pragma unroll
                for (int j = 0; j < 6; j++) {
                    float4 s4 = ld4(&sxc[r][lane * 4 + 128 * j]);
                    p += w4[j].x * s4.x + w4[j].y * s4.y +
                         w4[j].z * s4.z + w4[j].w * s4.w;
                }
#pragma unroll
                for (int m = 16; m; m >>= 1) p += __shfl_xor_sync(0xffffffffu, p, m);
                if (lane == 0) sdb[r * 56 + e] = p;
            }
        }
    }
    __syncthreads();

    {
        int r = tid >> 5, n = tid & 31;       // XR*32 = 256 threads exactly
        int l = l0 + r;
        if (l < LQ) g_bc[br][(size_t)(b * LQ + l) * 32 + n] = sdb[r * 56 + 24 + n];
    }

    const float* dw = br ? dwb : dwf;
    const float* db = br ? dbb : dbf;
    for (int d = tid; d < DIN; d += 256) {
        float4 w4[6];
#pragma unroll
        for (int j = 0; j < 6; j++) w4[j] = ld4(&dw[(size_t)d * DTR + j * 4]);
        float bias = db[d];
#pragma unroll
        for (int r = 0; r < XR; r++) {
            int l = l0 + r;
            if (l >= LQ) break;
            const float* sp = &sdb[r * 56];
            float acc = bias;
#pragma unroll
            for (int j = 0; j < 6; j++) {
                acc += w4[j].x * sp[j * 4 + 0] + w4[j].y * sp[j * 4 + 1] +
                       w4[j].z * sp[j * 4 + 2] + w4[j].w * sp[j * 4 + 3];
            }
            float spv = (acc > 20.f) ? acc : log1pf(__expf(acc));
            g_dt[br][(size_t)(b * LQ + l) * DIN + d] = spv;
        }
    }
}

// ------------------ selective scan ------------------
__global__ void k_ssm(const float* __restrict__ Alf, const float* __restrict__ Alb,
                      const float* __restrict__ Dpf, const float* __restrict__ Dpb) {
    __shared__ __align__(16) float sBC[LQ][32];
    int chunk = blockIdx.x;
    int b = blockIdx.y, br = blockIdx.z;
    int tid = threadIdx.x;
    int n = tid & 15, dl = tid >> 4;
    int d = chunk * 16 + dl;
    const float4* bcb4 = (const float4*)(g_bc[br] + (size_t)b * LQ * 32);
    float4* sBC4 = (float4*)sBC;
    for (int i = tid; i < LQ * 8; i += 256) sBC4[i] = bcb4[i];
    const float* Al = br ? Alb : Alf;
    float A = -__expf(Al[(size_t)d * NST + n]);
    float Dv = (br ? Dpb : Dpf)[d];
    const float* dtp = g_dt[br] + (size_t)b * LQ * DIN + d;
    const float* xcp = g_xc[br] + (size_t)b * LQ * DIN + d;
    float* yp = g_y[br] + (size_t)b * LQ * DIN + d;
    __syncthreads();
    float h = 0.f;
    float dt0 = dtp[0], xc0 = xcp[0];
    float dt1 = dtp[DIN], xc1 = xcp[DIN];
    for (int t = 0; t < LQ; t++) {
        float dtv = dt0, xv = xc0;
        dt0 = dt1; xc0 = xc1;
        int tp = (t + 2 < LQ) ? t + 2 : LQ - 1;
        dt1 = dtp[(size_t)tp * DIN];
        xc1 = xcp[(size_t)tp * DIN];
        float dA = __expf(dtv * A);
        h = dA * h + dtv * sBC[t][n] * xv;
        float p = h * sBC[t][16 + n];
        p += __shfl_xor_sync(0xffffffffu, p, 8);
        p += __shfl_xor_sync(0xffffffffu, p, 4);
        p += __shfl_xor_sync(0xffffffffu, p, 2);
        p += __shfl_xor_sync(0xffffffffu, p, 1);
        if (n == 0) yp[(size_t)t * DIN] = p + xv * Dv;   // gate applied in k_prepA1
    }
}

// ------------------ final residual + LN + cmd MLP head ------------------
__global__ void k_final(const float* __restrict__ sv, const float* __restrict__ av,
                        const float* __restrict__ lnw, const float* __restrict__ lnb,
                        const float* __restrict__ cw1, const float* __restrict__ cb1,
                        const float* __restrict__ cw2, const float* __restrict__ cb2,
                        float* __restrict__ out) {
    int b = blockIdx.x, tid = threadIdx.x;   // 384 threads
    __shared__ float c1[DMODEL], svis[DMODEL], cmdv[20], red[12];
    int row = b * LQ + POSI;
    float x = g_resid[(size_t)row * DMODEL + tid] +
              g_hid[0][(size_t)row * DMODEL + tid] +
              g_hid[1][(size_t)row * DMODEL + tid];
    float s = x;
#pragma unroll
    for (int m = 16; m; m >>= 1) s += __shfl_xor_sync(0xffffffffu, s, m);
    if ((tid & 31) == 0) red[tid >> 5] = s;
    __syncthreads();
    float tot = 0.f;
#pragma unroll
    for (int i = 0; i < 12; i++) tot += red[i];
    float mean = tot * (1.0f / DMODEL);
    float dv = x - mean;
    float vsq = dv * dv;
    __syncthreads();
#pragma unroll
    for (int m = 16; m; m >>= 1) vsq += __shfl_xor_sync(0xffffffffu, vsq, m);
    if ((tid & 31) == 0) red[tid >> 5] = vsq;
    __syncthreads();
    float vt = 0.f;
#pragma unroll
    for (int i = 0; i < 12; i++) vt += red[i];
    svis[tid] = dv * rsqrtf(vt * (1.0f / DMODEL) + 1e-5f) * lnw[tid] + lnb[tid];
    if (tid < 20) cmdv[tid] = (tid < 16) ? sv[b * 16 + tid] : av[b * 4 + tid - 16];
    __syncthreads();
    float a1 = cb1[tid];
#pragma unroll
    for (int k = 0; k < 20; k++) a1 += cmdv[k] * cw1[tid * 20 + k];
    c1[tid] = fmaxf(a1, 0.f);
    __syncthreads();
    int w = tid >> 5, lane = tid & 31;
    for (int r = w; r < DMODEL; r += 12) {
        float p = 0.f;
        const float* wr = cw2 + (size_t)r * DMODEL;
#pragma unroll
        for (int j = 0; j < 12; j++) p += c1[lane + 32 * j] * wr[lane + 32 * j];
#pragma unroll
        for (int m = 16; m; m >>= 1) p += __shfl_xor_sync(0xffffffffu, p, m);
        if (lane == 0) out[b * DMODEL + r] = svis[r] + p + cb2[r];
    }
}

// ------------------ host ------------------
extern "C" void kernel_launch(void* const* d_in, const int* in_sizes, int n_in,
                              void* d_out, int out_size) {
    const float* depth  = (const float*)d_in[0];
    const float* state  = (const float*)d_in[1];
    const float* action = (const float*)d_in[2];
    const float* patchw = (const float*)d_in[3];
    const float* patchb = (const float*)d_in[4];
    const float* cls    = (const float*)d_in[5];
    const float* pos    = (const float*)d_in[6];
    const float* lnw    = (const float*)d_in[7];
    const float* lnb    = (const float*)d_in[8];
    const float* inpw   = (const float*)d_in[9];
    const float* convw  = (const float*)d_in[10];
    const float* convb  = (const float*)d_in[11];
    const float* convwb = (const float*)d_in[12];
    const float* convbb = (const float*)d_in[13];
    const float* xpw    = (const float*)d_in[14];
    const float* xpwb   = (const float*)d_in[15];
    const float* dtw    = (const float*)d_in[16];
    const float* dtbv   = (const float*)d_in[17];
    const float* dtwb   = (const float*)d_in[18];
    const float* dtbb   = (const float*)d_in[19];
    const float* Alog   = (const float*)d_in[20];
    const float* Alogb  = (const float*)d_in[21];
    const float* Dp     = (const float*)d_in[22];
    const float* Dpb    = (const float*)d_in[23];
    const float* outw   = (const float*)d_in[24];
    const float* lnfw   = (const float*)d_in[25];
    const float* lnfb   = (const float*)d_in[26];
    const float* cw1    = (const float*)d_in[27];
    const float* cb1    = (const float*)d_in[28];
    const float* cw2    = (const float*)d_in[29];
    const float* cb2    = (const float*)d_in[30];

    float *p_tok, *p_xz, *p_hid;
    __nv_bfloat16 *p_wp_hi, *p_wp_lo, *p_win_hi, *p_win_lo, *p_wout_hi, *p_wout_lo;
    __nv_bfloat16 *p_a_hi, *p_a_lo, *p_p_hi, *p_p_lo;
    cudaGetSymbolAddress((void**)&p_tok, g_tok);
    cudaGetSymbolAddress((void**)&p_xz, g_xz);
    cudaGetSymbolAddress((void**)&p_hid, g_hid);
    cudaGetSymbolAddress((void**)&p_wp_hi, gwp_hi);
    cudaGetSymbolAddress((void**)&p_wp_lo, gwp_lo);
    cudaGetSymbolAddress((void**)&p_win_hi, gwin_hi);
    cudaGetSymbolAddress((void**)&p_win_lo, gwin_lo);
    cudaGetSymbolAddress((void**)&p_wout_hi, gwout_hi);
    cudaGetSymbolAddress((void**)&p_wout_lo, gwout_lo);
    cudaGetSymbolAddress((void**)&p_a_hi, ga_hi);
    cudaGetSymbolAddress((void**)&p_a_lo, ga_lo);
    cudaGetSymbolAddress((void**)&p_p_hi, gp_hi);
    cudaGetSymbolAddress((void**)&p_p_lo, gp_lo);

    cudaFuncSetAttribute(k_mma, cudaFuncAttributeMaxDynamicSharedMemorySize, SMEM_SZ);

    // merged prep: weight splits + patch gather (1 launch)
    k_prep<<<1024, 256>>>(patchw, inpw, outw, depth);

    // patch embed: M=1024, N=384, K=256
    k_mma<<<dim3(6, 16, 1), 256, SMEM_SZ>>>(p_p_hi, p_p_lo, p_wp_hi, p_wp_lo,
                                            p_tok, BATCH * NTOK, DMODEL, 256, 256, 4);

    for (int i = 0; i < 4; i++) {
        // layer 0: assemble (tok+cls+pos) fused into lnadd mode 0
        k_lnadd<<<(BL + 7) / 8, 256>>>(i == 0 ? 0 : 1,
                                       lnw + i * DMODEL, lnb + i * DMODEL,
                                       cls, pos, patchb);
        // in_proj: M=1028, N=1536, K=384
        k_mma<<<dim3(24, 17, 1), 256, SMEM_SZ>>>(
            p_a_hi, p_a_lo,
            p_win_hi + (size_t)i * 2 * DIN * DMODEL,
            p_win_lo + (size_t)i * 2 * DIN * DMODEL,
            p_xz, BL, 2 * DIN, DMODEL, DMODEL, 6);
        k_xproj<<<dim3((LQ + XR - 1) / XR, BATCH, 2), 256>>>(
            convw + i * DIN * KCONV, convb + i * DIN,
            convwb + i * DIN * KCONV, convbb + i * DIN,
            xpw + (size_t)i * 56 * DIN, xpwb + (size_t)i * 56 * DIN,
            dtw + (size_t)i * DIN * DTR, dtbv + i * DIN,
            dtwb + (size_t)i * DIN * DTR, dtbb + i * DIN);
        k_ssm<<<dim3(DIN / 16, BATCH, 2), 256>>>(
            Alog + (size_t)i * DIN * NST, Alogb + (size_t)i * DIN * NST,
            Dp + i * DIN, Dpb + i * DIN);
        k_prepA1<<<BL, 192>>>();
        // out_proj: M=1028, N=384, K=768, split-K=2 via blockIdx.z
        k_mma<<<dim3(6, 17, 2), 256, SMEM_SZ>>>(
            p_a_hi, p_a_lo,
            p_wout_hi + (size_t)i * DMODEL * DIN,
            p_wout_lo + (size_t)i * DMODEL * DIN,
            p_hid, BL, DMODEL, DIN, DIN, 6);
    }

    k_final<<<BATCH, DMODEL>>>(state, action, lnfw, lnfb, cw1, cb1, cw2, cb2,
                               (float*)d_out);
}

// round 16
// speedup vs baseline: 1.5023x; 1.0448x over previous
#include <cuda_runtime.h>
#include <cuda_bf16.h>
#include <cstdint>
#include <math.h>

#define BATCH 4
#define LQ 257        // NTOK+1
#define DMODEL 384
#define DIN 768
#define NST 16
#define DTR 24
#define KCONV 4
#define NTOK 256
#define POSI 128
#define BL (BATCH*LQ)   // 1028
#define XR 8            // xproj row tile

// ------------------ scratch (no allocations allowed) ------------------
__device__ float g_tok[BATCH*NTOK*DMODEL];
__device__ float g_resid[BL*DMODEL];
__device__ float g_hid[2][BL*DMODEL];       // split-K partials of out_proj
__device__ float g_xz[BL*2*DIN];
__device__ float g_xc[2][BL*DIN];
__device__ float g_dt[2][BL*DIN];
__device__ float g_bc[2][BL*2*NST];
__device__ float g_y[2][BL*DIN];

// bf16 hi/lo planes for tensor-core GEMMs
__device__ __nv_bfloat16 gwp_hi[DMODEL*256],       gwp_lo[DMODEL*256];
__device__ __nv_bfloat16 gwin_hi[4*2*DIN*DMODEL],  gwin_lo[4*2*DIN*DMODEL];
__device__ __nv_bfloat16 gwout_hi[4*DMODEL*DIN],   gwout_lo[4*DMODEL*DIN];
__device__ __nv_bfloat16 ga_hi[BL*DIN],            ga_lo[BL*DIN];
__device__ __nv_bfloat16 gp_hi[BATCH*NTOK*256],    gp_lo[BATCH*NTOK*256];

__device__ __forceinline__ float4 ld4(const float* p) {
    return *reinterpret_cast<const float4*>(p);
}

// ------------------ hi/lo split helpers ------------------
__device__ __forceinline__ void split_bf16(float x, __nv_bfloat16* hi,
                                           __nv_bfloat16* lo) {
    __nv_bfloat16 h = __float2bfloat16(x);
    *hi = h;
    *lo = __float2bfloat16(x - __bfloat162float(h));
}

// ================== mma.sync GEMM machinery (base sm_103 ISA) ==================
// Tile 64x64, chunk K=64.  Buffer layout (32 KB each, double buffered):
//   A_hi [0,8K) A_lo [8K,16K) B_hi [16K,24K) B_lo [24K,32K)
#define BUFB 32768
#define SMEM_SZ (1024 + 2*BUFB)   // 66560

__device__ __forceinline__ uint32_t smem_u32(const void* p) {
    uint32_t a;
    asm("{ .reg .u64 t; cvta.to.shared.u64 t, %1; cvt.u32.u64 %0, t; }"
        : "=r"(a) : "l"(p));
    return a;
}
__device__ __forceinline__ void ldmx4(uint32_t* r, uint32_t addr) {
    asm volatile("ldmatrix.sync.aligned.m8n8.x4.shared.b16 {%0,%1,%2,%3}, [%4];"
        : "=r"(r[0]), "=r"(r[1]), "=r"(r[2]), "=r"(r[3]) : "r"(addr));
}
__device__ __forceinline__ void mma16816(float* c, const uint32_t* a,
                                         const uint32_t* b) {
    asm volatile(
        "mma.sync.aligned.m16n8k16.row.col.f32.bf16.bf16.f32 "
        "{%0,%1,%2,%3}, {%4,%5,%6,%7}, {%8,%9}, {%0,%1,%2,%3};"
        : "+f"(c[0]), "+f"(c[1]), "+f"(c[2]), "+f"(c[3])
        : "r"(a[0]), "r"(a[1]), "r"(a[2]), "r"(a[3]), "r"(b[0]), "r"(b[1]));
}
// .cg (L2-only): .ca measured slower (L1 alloc contention with ldmatrix)
__device__ __forceinline__ void cpa16(uint32_t dst, const void* src, int nbytes) {
    asm volatile("cp.async.cg.shared.global [%0], [%1], 16, %2;"
        :: "r"(dst), "l"(src), "r"(nbytes));
}

// issue one K-chunk's loads into buffer (c & 1)
__device__ __forceinline__ void mma_issue(
    uint32_t base, int c, int tid, int m0, int n0, int koff, int M,
    const __nv_bfloat16* ah, const __nv_bfloat16* al,
    const __nv_bfloat16* wh, const __nv_bfloat16* wl, int aK, int wK)
{
    uint32_t boff = base + (c & 1) * BUFB;
    int k0 = koff + c * 64;
#pragma unroll
    for (int s = 0; s < 2; s++) {
        int idx = tid + s * 256;
        int row = idx >> 3, ch = idx & 7;
        int m = m0 + row;
        int ok = (m < M) ? 16 : 0;
        size_t moff = (size_t)(ok ? m : 0) * aK + k0 + ch * 8;
        uint32_t so = (uint32_t)(row * 128 + ch * 16);
        so ^= (so >> 3) & 0x70;
        cpa16(boff + so, ah + moff, ok);
        cpa16(boff + 8192 + so, al + moff, ok);
    }
#pragma unroll
    for (int s = 0; s < 2; s++) {
        int idx = tid + s * 256;
        int row = idx >> 3, ch = idx & 7;
        size_t noff = (size_t)(n0 + row) * wK + k0 + ch * 8;
        uint32_t so = (uint32_t)(row * 128 + ch * 16);
        so ^= (so >> 3) & 0x70;
        cpa16(boff + 16384 + so, wh + noff, 16);
        cpa16(boff + 24576 + so, wl + noff, 16);
    }
    asm volatile("cp.async.commit_group;");
}

// C[M,N] = A[M,K] * W[N,K]^T  via split-bf16 mma.sync.
// 8 warps as 4(m) x 2(n); warp tile 16 rows x 32 cols.
__global__ __launch_bounds__(256, 3)
void k_mma(const __nv_bfloat16* __restrict__ ah, const __nv_bfloat16* __restrict__ al,
           const __nv_bfloat16* __restrict__ wh, const __nv_bfloat16* __restrict__ wl,
           float* __restrict__ C, int M, int Nn, int aK, int wK, int nchunks)
{
    extern __shared__ char smraw[];
    uint32_t raw = smem_u32(smraw);
    uint32_t base = (raw + 1023) & ~1023u;
    int tid = threadIdx.x, wid = tid >> 5, lane = tid & 31;
    int m0 = blockIdx.y * 64, n0 = blockIdx.x * 64;
    int koff = blockIdx.z * nchunks * 64;
    C += (size_t)blockIdx.z * M * Nn;
    int wm = wid & 3, wn = wid >> 2;     // warp tile: rows wm*16, cols wn*32

    float acc[4][4] = {};                // [nt][frag]

    mma_issue(base, 0, tid, m0, n0, koff, M, ah, al, wh, wl, aK, wK);
    if (nchunks > 1)
        mma_issue(base, 1, tid, m0, n0, koff, M, ah, al, wh, wl, aK, wK);

    for (int c = 0; c < nchunks; c++) {
        if (c + 1 < nchunks) asm volatile("cp.async.wait_group 1;");
        else                 asm volatile("cp.async.wait_group 0;");
        __syncthreads();
        uint32_t boff = base + (c & 1) * BUFB;

#pragma unroll
        for (int ks = 0; ks < 4; ks++) {
            uint32_t a_hi[4], a_lo[4];
            {
                uint32_t row = (uint32_t)(wm * 16 + (lane & 15));
                uint32_t colb = (uint32_t)(ks * 32 + ((lane >> 4) << 4));
                uint32_t so = row * 128 + colb;
                so ^= (so >> 3) & 0x70;
                ldmx4(a_hi, boff + so);
                ldmx4(a_lo, boff + 8192 + so);
            }
            // B: one ldmx4 covers an nt pair (16 rows x 16 cols)
            uint32_t b_hi[4][2], b_lo[4][2];
#pragma unroll
            for (int pp = 0; pp < 2; pp++) {
                uint32_t row = (uint32_t)(wn * 32 + pp * 16 +
                                          ((lane >> 4) << 3) + (lane & 7));
                uint32_t colb = (uint32_t)(ks * 32 + (((lane >> 3) & 1) << 4));
                uint32_t so = row * 128 + colb;
                so ^= (so >> 3) & 0x70;
                uint32_t rh[4], rl[4];
                ldmx4(rh, boff + 16384 + so);
                ldmx4(rl, boff + 24576 + so);
                b_hi[2*pp][0] = rh[0]; b_hi[2*pp][1] = rh[1];
                b_hi[2*pp+1][0] = rh[2]; b_hi[2*pp+1][1] = rh[3];
                b_lo[2*pp][0] = rl[0]; b_lo[2*pp][1] = rl[1];
                b_lo[2*pp+1][0] = rl[2]; b_lo[2*pp+1][1] = rl[3];
            }
#pragma unroll
            for (int nt = 0; nt < 4; nt++) {
                mma16816(acc[nt], a_hi, b_hi[nt]);
                mma16816(acc[nt], a_hi, b_lo[nt]);
                mma16816(acc[nt], a_lo, b_hi[nt]);
            }
        }
        if (c + 2 < nchunks) {
            __syncthreads();   // buffer (c&1) free only after all warps consumed it
            mma_issue(base, c + 2, tid, m0, n0, koff, M, ah, al, wh, wl, aK, wK);
        }
    }

    // ---- epilogue: each warp writes its 16x32 tile ----
#pragma unroll
    for (int nt = 0; nt < 4; nt++) {
        int m = m0 + wm * 16 + (lane >> 2);
        int n = n0 + wn * 32 + nt * 8 + (lane & 3) * 2;
        if (m < M)
            *(float2*)(C + (size_t)m * Nn + n) = make_float2(acc[nt][0], acc[nt][1]);
        if (m + 8 < M)
            *(float2*)(C + (size_t)(m + 8) * Nn + n) = make_float2(acc[nt][2], acc[nt][3]);
    }
}

__device__ __forceinline__ void split4_store(float4 v, __nv_bfloat16* hp,
                                             __nv_bfloat16* lp, size_t off) {
    __nv_bfloat16 hh[4], ll[4];
    split_bf16(v.x, &hh[0], &ll[0]);
    split_bf16(v.y, &hh[1], &ll[1]);
    split_bf16(v.z, &hh[2], &ll[2]);
    split_bf16(v.w, &hh[3], &ll[3]);
    *(uint2*)(hp + off) = *(uint2*)hh;
    *(uint2*)(lp + off) = *(uint2*)ll;
}

// ------------------ merged prep: all weight splits + patch gather ------------------
#define NP0 (DMODEL*256/4)                  // patchw f4s   (24576)
#define NP1 (4*2*DIN*DMODEL/4)              // inpw f4s     (589824)
#define NP2 (4*DMODEL*DIN/4)                // outw f4s     (294912)
#define NP3 (BATCH*NTOK*256/4)              // patch gather (65536)
__global__ void k_prep(const float* __restrict__ patchw,
                       const float* __restrict__ inpw,
                       const float* __restrict__ outw,
                       const float* __restrict__ depth) {
    const int total = NP0 + NP1 + NP2 + NP3;
    for (int i = blockIdx.x * 256 + threadIdx.x; i < total; i += gridDim.x * 256) {
        if (i < NP0) {
            split4_store(ld4(patchw + (size_t)i * 4), gwp_hi, gwp_lo, (size_t)i * 4);
        } else if (i < NP0 + NP1) {
            size_t j = i - NP0;
            split4_store(ld4(inpw + j * 4), gwin_hi, gwin_lo, j * 4);
        } else if (i < NP0 + NP1 + NP2) {
            size_t j = i - NP0 - NP1;
            split4_store(ld4(outw + j * 4), gwout_hi, gwout_lo, j * 4);
        } else {
            int j = i - NP0 - NP1 - NP2;
            int m = j >> 6, k = (j & 63) * 4;       // row m of 256 cols, col k
            int b = m >> 8, p = m & 255;
            int ii = k >> 4, jj = k & 15;
            int gh = p >> 3, gw = p & 7;
            int row = gh * 16 + ii;
            int tt = row >> 7, hh = row & 127;
            int col = gw * 16 + jj;
            float4 v = ld4(depth + (size_t)(((b * 4 + tt) << 7) + hh) * 128 + col);
            split4_store(v, gp_hi, gp_lo, (size_t)m * 256 + k);
        }
    }
}

// combine + silu(z) gate + split  (A of out_proj, K=768), float4
__global__ void k_prepA1() {
    int m = blockIdx.x;                       // BL blocks x 192 threads
    int b = m / LQ, l = m - b * LQ;
    const float* yf = g_y[0] + (size_t)m * DIN;
    const float* yb = g_y[1] + (size_t)(b * LQ + (NTOK - l)) * DIN;
    const float* zp = g_xz + (size_t)m * (2 * DIN) + DIN;
    int k = threadIdx.x * 4;
    float4 z = ld4(zp + k), u = ld4(yf + k), v = ld4(yb + k);
    float4 x;
    x.x = (u.x + v.x) * (z.x / (1.f + __expf(-z.x)));
    x.y = (u.y + v.y) * (z.y / (1.f + __expf(-z.y)));
    x.z = (u.z + v.z) * (z.z / (1.f + __expf(-z.z)));
    x.w = (u.w + v.w) * (z.w / (1.f + __expf(-z.w)));
    split4_store(x, ga_hi, ga_lo, (size_t)m * DIN + k);
}

// ------------------ residual/assemble + LN -> split bf16 A (K=384) ------------------
// mode 0: assemble from tok/cls/pos (layer 0).  mode 1: add split-K partials.
__global__ void k_lnadd(int mode, const float* __restrict__ w,
                        const float* __restrict__ bb,
                        const float* __restrict__ cls,
                        const float* __restrict__ pos,
                        const float* __restrict__ pb) {
    int row = blockIdx.x * 8 + (threadIdx.x >> 5);
    int lane = threadIdx.x & 31;
    if (row >= BL) return;
    float* rp = g_resid + (size_t)row * DMODEL;
    float v[12];
    float s = 0.f;
    if (mode == 0) {
        int b = row / LQ, l = row - b * LQ;
#pragma unroll
        for (int q = 0; q < 12; q++) {
            int d = lane + 32 * q;
            float x;
            if (l == POSI) x = cls[d];
            else {
                int p = (l < POSI) ? l : (l - 1);
                x = g_tok[(size_t)(b * NTOK + p) * DMODEL + d] + pb[d];
            }
            x += pos[l * DMODEL + d];
            rp[d] = x;
            v[q] = x; s += x;
        }
    } else {
        const float* h0 = g_hid[0] + (size_t)row * DMODEL;
        const float* h1 = g_hid[1] + (size_t)row * DMODEL;
#pragma unroll
        for (int q = 0; q < 12; q++) {
            int d = lane + 32 * q;
            float x = rp[d] + h0[d] + h1[d];
            rp[d] = x;
            v[q] = x; s += x;
        }
    }
#pragma unroll
    for (int m = 16; m; m >>= 1) s += __shfl_xor_sync(0xffffffffu, s, m);
    float mean = s * (1.f / DMODEL);
    float sq = 0.f;
#pragma unroll
    for (int q = 0; q < 12; q++) { float dv = v[q] - mean; sq += dv * dv; }
#pragma unroll
    for (int m = 16; m; m >>= 1) sq += __shfl_xor_sync(0xffffffffu, sq, m);
    float rstd = rsqrtf(sq * (1.f / DMODEL) + 1e-5f);
#pragma unroll
    for (int q = 0; q < 12; q++) {
        int d = lane + 32 * q;
        float y = (v[q] - mean) * rstd * w[d] + bb[d];
        split_bf16(y, &ga_hi[(size_t)row * DMODEL + d],
                      &ga_lo[(size_t)row * DMODEL + d]);
    }
}

// ------------------ fused conv+silu -> xproj -> B,C -> dtproj+softplus ------------------
__global__ void k_xproj(const float* __restrict__ cwf, const float* __restrict__ cbf,
                        const float* __restrict__ cwb, const float* __restrict__ cbb,
                        const float* __restrict__ xwf, const float* __restrict__ xwb,
                        const float* __restrict__ dwf, const float* __restrict__ dbf,
                        const float* __restrict__ dwb, const float* __restrict__ dbb) {
    __shared__ __align__(16) float sxc[XR][DIN];
    __shared__ float sdb[XR * 56];
    int l0 = blockIdx.x * XR;
    int b = blockIdx.y, br = blockIdx.z;
    int tid = threadIdx.x;                 // 256
    const float* cw = br ? cwb : cwf;
    const float* cb = br ? cbb : cbf;

    // phase 0: conv + silu, sliding window over rows (each row loaded once)
    for (int d = tid; d < DIN; d += 256) {
        float4 wc = ld4(&cw[d * KCONV]);
        float wct[4] = {wc.x, wc.y, wc.z, wc.w};
        float bias = cb[d];
        float v[XR + 3];
#pragma unroll
        for (int j = 0; j < XR + 3; j++) {
            int idx = l0 - 3 + j;
            float x = 0.f;
            if (idx >= 0 && idx <= NTOK) {
                int src = br ? (NTOK - idx) : idx;
                x = g_xz[(size_t)(b * LQ + src) * (2 * DIN) + d];
            }
            v[j] = x;
        }
#pragma unroll
        for (int r = 0; r < XR; r++) {
            int l = l0 + r;
            float val = 0.f;
            if (l < LQ) {
                float acc = bias + wct[0] * v[r] + wct[1] * v[r + 1] +
                            wct[2] * v[r + 2] + wct[3] * v[r + 3];
                val = acc / (1.f + __expf(-acc));
                g_xc[br][(size_t)(b * LQ + l) * DIN + d] = val;
            }
            sxc[r][d] = val;
        }
    }
    __syncthreads();

    {
        const float* xw = br ? xwb : xwf;
        int wid = tid >> 5, lane = tid & 31;
        for (int e = wid; e < 56; e += 8) {
            float4 w4[6];
#pragma unroll
            for (int j = 0; j < 6; j++)
                w4[j] = ld4(&xw[(size_t)e * DIN + lane * 4 + 128 * j]);
#pragma unroll
            for (int r = 0; r < XR; r++) {
                float p = 0.f;
#pragma unroll
                for (int j = 0; j < 6; j++) {
                    float4 s4 = ld4(&sxc[r][lane * 4 + 128 * j]);
                    p += w4[j].x * s4.x + w4[j].y * s4.y +
                         w4[j].z * s4.z + w4[j].w * s4.w;
                }
#pragma unroll
                for (int m = 16; m; m >>= 1) p += __shfl_xor_sync(0xffffffffu, p, m);
                if (lane == 0) sdb[r * 56 + e] = p;
            }
        }
    }
    __syncthreads();

    {
        int r = tid >> 5, n = tid & 31;       // XR*32 = 256 threads exactly
        int l = l0 + r;
        if (l < LQ) g_bc[br][(size_t)(b * LQ + l) * 32 + n] = sdb[r * 56 + 24 + n];
    }

    const float* dw = br ? dwb : dwf;
    const float* db = br ? dbb : dbf;
    for (int d = tid; d < DIN; d += 256) {
        float4 w4[6];
#pragma unroll
        for (int j = 0; j < 6; j++) w4[j] = ld4(&dw[(size_t)d * DTR + j * 4]);
        float bias = db[d];
#pragma unroll
        for (int r = 0; r < XR; r++) {
            int l = l0 + r;
            if (l >= LQ) break;
            const float* sp = &sdb[r * 56];
            float acc = bias;
#pragma unroll
            for (int j = 0; j < 6; j++) {
                acc += w4[j].x * sp[j * 4 + 0] + w4[j].y * sp[j * 4 + 1] +
                       w4[j].z * sp[j * 4 + 2] + w4[j].w * sp[j * 4 + 3];
            }
            float spv = (acc > 20.f) ? acc : log1pf(__expf(acc));
            g_dt[br][(size_t)(b * LQ + l) * DIN + d] = spv;
        }
    }
}

// ------------------ selective scan ------------------
__global__ void k_ssm(const float* __restrict__ Alf, const float* __restrict__ Alb,
                      const float* __restrict__ Dpf, const float* __restrict__ Dpb) {
    __shared__ __align__(16) float sBC[LQ][32];
    int chunk = blockIdx.x;
    int b = blockIdx.y, br = blockIdx.z;
    int tid = threadIdx.x;
    int n = tid & 15, dl = tid >> 4;
    int d = chunk * 16 + dl;
    const float4* bcb4 = (const float4*)(g_bc[br] + (size_t)b * LQ * 32);
    float4* sBC4 = (float4*)sBC;
    for (int i = tid; i < LQ * 8; i += 256) sBC4[i] = bcb4[i];
    const float* Al = br ? Alb : Alf;
    float A = -__expf(Al[(size_t)d * NST + n]);
    float Dv = (br ? Dpb : Dpf)[d];
    const float* dtp = g_dt[br] + (size_t)b * LQ * DIN + d;
    const float* xcp = g_xc[br] + (size_t)b * LQ * DIN + d;
    float* yp = g_y[br] + (size_t)b * LQ * DIN + d;
    __syncthreads();
    float h = 0.f;
    float dt0 = dtp[0], xc0 = xcp[0];
    float dt1 = dtp[DIN], xc1 = xcp[DIN];
    for (int t = 0; t < LQ; t++) {
        float dtv = dt0, xv = xc0;
        dt0 = dt1; xc0 = xc1;
        int tp = (t + 2 < LQ) ? t + 2 : LQ - 1;
        dt1 = dtp[(size_t)tp * DIN];
        xc1 = xcp[(size_t)tp * DIN];
        float dA = __expf(dtv * A);
        h = dA * h + dtv * sBC[t][n] * xv;
        float p = h * sBC[t][16 + n];
        p += __shfl_xor_sync(0xffffffffu, p, 8);
        p += __shfl_xor_sync(0xffffffffu, p, 4);
        p += __shfl_xor_sync(0xffffffffu, p, 2);
        p += __shfl_xor_sync(0xffffffffu, p, 1);
        if (n == 0) yp[(size_t)t * DIN] = p + xv * Dv;   // gate applied in k_prepA1
    }
}

// ------------------ final residual + LN + cmd MLP head ------------------
__global__ void k_final(const float* __restrict__ sv, const float* __restrict__ av,
                        const float* __restrict__ lnw, const float* __restrict__ lnb,
                        const float* __restrict__ cw1, const float* __restrict__ cb1,
                        const float* __restrict__ cw2, const float* __restrict__ cb2,
                        float* __restrict__ out) {
    int b = blockIdx.x, tid = threadIdx.x;   // 384 threads
    __shared__ float c1[DMODEL], svis[DMODEL], cmdv[20], red[12];
    int row = b * LQ + POSI;
    float x = g_resid[(size_t)row * DMODEL + tid] +
              g_hid[0][(size_t)row * DMODEL + tid] +
              g_hid[1][(size_t)row * DMODEL + tid];
    float s = x;
#pragma unroll
    for (int m = 16; m; m >>= 1) s += __shfl_xor_sync(0xffffffffu, s, m);
    if ((tid & 31) == 0) red[tid >> 5] = s;
    __syncthreads();
    float tot = 0.f;
#pragma unroll
    for (int i = 0; i < 12; i++) tot += red[i];
    float mean = tot * (1.0f / DMODEL);
    float dv = x - mean;
    float vsq = dv * dv;
    __syncthreads();
#pragma unroll
    for (int m = 16; m; m >>= 1) vsq += __shfl_xor_sync(0xffffffffu, vsq, m);
    if ((tid & 31) == 0) red[tid >> 5] = vsq;
    __syncthreads();
    float vt = 0.f;
#pragma unroll
    for (int i = 0; i < 12; i++) vt += red[i];
    svis[tid] = dv * rsqrtf(vt * (1.0f / DMODEL) + 1e-5f) * lnw[tid] + lnb[tid];
    if (tid < 20) cmdv[tid] = (tid < 16) ? sv[b * 16 + tid] : av[b * 4 + tid - 16];
    __syncthreads();
    float a1 = cb1[tid];
#pragma unroll
    for (int k = 0; k < 20; k++) a1 += cmdv[k] * cw1[tid * 20 + k];
    c1[tid] = fmaxf(a1, 0.f);
    __syncthreads();
    int w = tid >> 5, lane = tid & 31;
    for (int r = w; r < DMODEL; r += 12) {
        float p = 0.f;
        const float* wr = cw2 + (size_t)r * DMODEL;
#pragma unroll
        for (int j = 0; j < 12; j++) p += c1[lane + 32 * j] * wr[lane + 32 * j];
#pragma unroll
        for (int m = 16; m; m >>= 1) p += __shfl_xor_sync(0xffffffffu, p, m);
        if (lane == 0) out[b * DMODEL + r] = svis[r] + p + cb2[r];
    }
}

// ------------------ host ------------------
extern "C" void kernel_launch(void* const* d_in, const int* in_sizes, int n_in,
                              void* d_out, int out_size) {
    const float* depth  = (const float*)d_in[0];
    const float* state  = (const float*)d_in[1];
    const float* action = (const float*)d_in[2];
    const float* patchw = (const float*)d_in[3];
    const float* patchb = (const float*)d_in[4];
    const float* cls    = (const float*)d_in[5];
    const float* pos    = (const float*)d_in[6];
    const float* lnw    = (const float*)d_in[7];
    const float* lnb    = (const float*)d_in[8];
    const float* inpw   = (const float*)d_in[9];
    const float* convw  = (const float*)d_in[10];
    const float* convb  = (const float*)d_in[11];
    const float* convwb = (const float*)d_in[12];
    const float* convbb = (const float*)d_in[13];
    const float* xpw    = (const float*)d_in[14];
    const float* xpwb   = (const float*)d_in[15];
    const float* dtw    = (const float*)d_in[16];
    const float* dtbv   = (const float*)d_in[17];
    const float* dtwb   = (const float*)d_in[18];
    const float* dtbb   = (const float*)d_in[19];
    const float* Alog   = (const float*)d_in[20];
    const float* Alogb  = (const float*)d_in[21];
    const float* Dp     = (const float*)d_in[22];
    const float* Dpb    = (const float*)d_in[23];
    const float* outw   = (const float*)d_in[24];
    const float* lnfw   = (const float*)d_in[25];
    const float* lnfb   = (const float*)d_in[26];
    const float* cw1    = (const float*)d_in[27];
    const float* cb1    = (const float*)d_in[28];
    const float* cw2    = (const float*)d_in[29];
    const float* cb2    = (const float*)d_in[30];

    float *p_tok, *p_xz, *p_hid;
    __nv_bfloat16 *p_wp_hi, *p_wp_lo, *p_win_hi, *p_win_lo, *p_wout_hi, *p_wout_lo;
    __nv_bfloat16 *p_a_hi, *p_a_lo, *p_p_hi, *p_p_lo;
    cudaGetSymbolAddress((void**)&p_tok, g_tok);
    cudaGetSymbolAddress((void**)&p_xz, g_xz);
    cudaGetSymbolAddress((void**)&p_hid, g_hid);
    cudaGetSymbolAddress((void**)&p_wp_hi, gwp_hi);
    cudaGetSymbolAddress((void**)&p_wp_lo, gwp_lo);
    cudaGetSymbolAddress((void**)&p_win_hi, gwin_hi);
    cudaGetSymbolAddress((void**)&p_win_lo, gwin_lo);
    cudaGetSymbolAddress((void**)&p_wout_hi, gwout_hi);
    cudaGetSymbolAddress((void**)&p_wout_lo, gwout_lo);
    cudaGetSymbolAddress((void**)&p_a_hi, ga_hi);
    cudaGetSymbolAddress((void**)&p_a_lo, ga_lo);
    cudaGetSymbolAddress((void**)&p_p_hi, gp_hi);
    cudaGetSymbolAddress((void**)&p_p_lo, gp_lo);

    cudaFuncSetAttribute(k_mma, cudaFuncAttributeMaxDynamicSharedMemorySize, SMEM_SZ);

    // merged prep: weight splits + patch gather (1 launch)
    k_prep<<<1024, 256>>>(patchw, inpw, outw, depth);

    // patch embed: M=1024, N=384, K=256
    k_mma<<<dim3(6, 16, 1), 256, SMEM_SZ>>>(p_p_hi, p_p_lo, p_wp_hi, p_wp_lo,
                                            p_tok, BATCH * NTOK, DMODEL, 256, 256, 4);

    for (int i = 0; i < 4; i++) {
        // layer 0: assemble (tok+cls+pos) fused into lnadd mode 0
        k_lnadd<<<(BL + 7) / 8, 256>>>(i == 0 ? 0 : 1,
                                       lnw + i * DMODEL, lnb + i * DMODEL,
                                       cls, pos, patchb);
        // in_proj: M=1028, N=1536, K=384
        k_mma<<<dim3(24, 17, 1), 256, SMEM_SZ>>>(
            p_a_hi, p_a_lo,
            p_win_hi + (size_t)i * 2 * DIN * DMODEL,
            p_win_lo + (size_t)i * 2 * DIN * DMODEL,
            p_xz, BL, 2 * DIN, DMODEL, DMODEL, 6);
        k_xproj<<<dim3((LQ + XR - 1) / XR, BATCH, 2), 256>>>(
            convw + i * DIN * KCONV, convb + i * DIN,
            convwb + i * DIN * KCONV, convbb + i * DIN,
            xpw + (size_t)i * 56 * DIN, xpwb + (size_t)i * 56 * DIN,
            dtw + (size_t)i * DIN * DTR, dtbv + i * DIN,
            dtwb + (size_t)i * DIN * DTR, dtbb + i * DIN);
        k_ssm<<<dim3(DIN / 16, BATCH, 2), 256>>>(
            Alog + (size_t)i * DIN * NST, Alogb + (size_t)i * DIN * NST,
            Dp + i * DIN, Dpb + i * DIN);
        k_prepA1<<<BL, 192>>>();
        // out_proj: M=1028, N=384, K=768, split-K=2 via blockIdx.z
        k_mma<<<dim3(6, 17, 2), 256, SMEM_SZ>>>(
            p_a_hi, p_a_lo,
            p_wout_hi + (size_t)i * DMODEL * DIN,
            p_wout_lo + (size_t)i * DMODEL * DIN,
            p_hid, BL, DMODEL, DIN, DIN, 6);
    }

    k_final<<<BATCH, DMODEL>>>(state, action, lnfw, lnfb, cw1, cb1, cw2, cb2,
                               (float*)d_out);
}

// round 17
// speedup vs baseline: 1.8362x; 1.2222x over previous
#include <cuda_runtime.h>
#include <cuda_bf16.h>
#include <cstdint>
#include <math.h>

#define BATCH 4
#define LQ 257        // NTOK+1
#define DMODEL 384
#define DIN 768
#define NST 16
#define DTR 24
#define KCONV 4
#define NTOK 256
#define POSI 128
#define BL (BATCH*LQ)   // 1028
#define XR 8            // xproj row tile

// ------------------ scratch (no allocations allowed) ------------------
__device__ float g_tok[BATCH*NTOK*DMODEL];
__device__ float g_resid[BL*DMODEL];
__device__ float g_hid[2][BL*DMODEL];       // split-K partials of out_proj
__device__ float g_xz[BL*2*DIN];
__device__ float g_xc[2][BL*DIN];
__device__ float g_dt[2][BL*DIN];
__device__ float g_bc[2][BL*2*NST];
__device__ float g_y[2][BL*DIN];

// bf16 hi/lo planes for tensor-core GEMMs
__device__ __nv_bfloat16 gwp_hi[DMODEL*256],       gwp_lo[DMODEL*256];
__device__ __nv_bfloat16 gwin_hi[4*2*DIN*DMODEL],  gwin_lo[4*2*DIN*DMODEL];
__device__ __nv_bfloat16 gwout_hi[4*DMODEL*DIN],   gwout_lo[4*DMODEL*DIN];
__device__ __nv_bfloat16 ga_hi[BL*DIN],            ga_lo[BL*DIN];
__device__ __nv_bfloat16 gp_hi[BATCH*NTOK*256],    gp_lo[BATCH*NTOK*256];

__device__ __forceinline__ float4 ld4(const float* p) {
    return *reinterpret_cast<const float4*>(p);
}

// ------------------ hi/lo split helpers ------------------
__device__ __forceinline__ void split_bf16(float x, __nv_bfloat16* hi,
                                           __nv_bfloat16* lo) {
    __nv_bfloat16 h = __float2bfloat16(x);
    *hi = h;
    *lo = __float2bfloat16(x - __bfloat162float(h));
}

// ================== mma.sync GEMM machinery (base sm_103 ISA) ==================
// Tile 64x64, chunk K=64.  Buffer layout (32 KB each, double buffered):
//   A_hi [0,8K) A_lo [8K,16K) B_hi [16K,24K) B_lo [24K,32K)
#define BUFB 32768
#define SMEM_SZ (1024 + 2*BUFB)   // 66560

__device__ __forceinline__ uint32_t smem_u32(const void* p) {
    uint32_t a;
    asm("{ .reg .u64 t; cvta.to.shared.u64 t, %1; cvt.u32.u64 %0, t; }"
        : "=r"(a) : "l"(p));
    return a;
}
__device__ __forceinline__ void ldmx4(uint32_t* r, uint32_t addr) {
    asm volatile("ldmatrix.sync.aligned.m8n8.x4.shared.b16 {%0,%1,%2,%3}, [%4];"
        : "=r"(r[0]), "=r"(r[1]), "=r"(r[2]), "=r"(r[3]) : "r"(addr));
}
__device__ __forceinline__ void mma16816(float* c, const uint32_t* a,
                                         const uint32_t* b) {
    asm volatile(
        "mma.sync.aligned.m16n8k16.row.col.f32.bf16.bf16.f32 "
        "{%0,%1,%2,%3}, {%4,%5,%6,%7}, {%8,%9}, {%0,%1,%2,%3};"
        : "+f"(c[0]), "+f"(c[1]), "+f"(c[2]), "+f"(c[3])
        : "r"(a[0]), "r"(a[1]), "r"(a[2]), "r"(a[3]), "r"(b[0]), "r"(b[1]));
}
// .cg (L2-only): .ca measured slower (L1 alloc contention with ldmatrix)
__device__ __forceinline__ void cpa16(uint32_t dst, const void* src, int nbytes) {
    asm volatile("cp.async.cg.shared.global [%0], [%1], 16, %2;"
        :: "r"(dst), "l"(src), "r"(nbytes));
}

// issue one K-chunk's loads into buffer (c & 1)
__device__ __forceinline__ void mma_issue(
    uint32_t base, int c, int tid, int m0, int n0, int koff, int M,
    const __nv_bfloat16* ah, const __nv_bfloat16* al,
    const __nv_bfloat16* wh, const __nv_bfloat16* wl, int aK, int wK)
{
    uint32_t boff = base + (c & 1) * BUFB;
    int k0 = koff + c * 64;
#pragma unroll
    for (int s = 0; s < 2; s++) {
        int idx = tid + s * 256;
        int row = idx >> 3, ch = idx & 7;
        int m = m0 + row;
        int ok = (m < M) ? 16 : 0;
        size_t moff = (size_t)(ok ? m : 0) * aK + k0 + ch * 8;
        uint32_t so = (uint32_t)(row * 128 + ch * 16);
        so ^= (so >> 3) & 0x70;
        cpa16(boff + so, ah + moff, ok);
        cpa16(boff + 8192 + so, al + moff, ok);
    }
#pragma unroll
    for (int s = 0; s < 2; s++) {
        int idx = tid + s * 256;
        int row = idx >> 3, ch = idx & 7;
        size_t noff = (size_t)(n0 + row) * wK + k0 + ch * 8;
        uint32_t so = (uint32_t)(row * 128 + ch * 16);
        so ^= (so >> 3) & 0x70;
        cpa16(boff + 16384 + so, wh + noff, 16);
        cpa16(boff + 24576 + so, wl + noff, 16);
    }
    asm volatile("cp.async.commit_group;");
}

// C[M,N] = A[M,K] * W[N,K]^T  via split-bf16 mma.sync.
// 8 warps as 4(m) x 2(n); warp tile 16 rows x 32 cols.
__global__ __launch_bounds__(256, 3)
void k_mma(const __nv_bfloat16* __restrict__ ah, const __nv_bfloat16* __restrict__ al,
           const __nv_bfloat16* __restrict__ wh, const __nv_bfloat16* __restrict__ wl,
           float* __restrict__ C, int M, int Nn, int aK, int wK, int nchunks)
{
    extern __shared__ char smraw[];
    uint32_t raw = smem_u32(smraw);
    uint32_t base = (raw + 1023) & ~1023u;
    int tid = threadIdx.x, wid = tid >> 5, lane = tid & 31;
    int m0 = blockIdx.y * 64, n0 = blockIdx.x * 64;
    int koff = blockIdx.z * nchunks * 64;
    C += (size_t)blockIdx.z * M * Nn;
    int wm = wid & 3, wn = wid >> 2;     // warp tile: rows wm*16, cols wn*32

    float acc[4][4] = {};                // [nt][frag]

    mma_issue(base, 0, tid, m0, n0, koff, M, ah, al, wh, wl, aK, wK);
    if (nchunks > 1)
        mma_issue(base, 1, tid, m0, n0, koff, M, ah, al, wh, wl, aK, wK);

    for (int c = 0; c < nchunks; c++) {
        if (c + 1 < nchunks) asm volatile("cp.async.wait_group 1;");
        else                 asm volatile("cp.async.wait_group 0;");
        __syncthreads();
        uint32_t boff = base + (c & 1) * BUFB;

#pragma unroll
        for (int ks = 0; ks < 4; ks++) {
            uint32_t a_hi[4], a_lo[4];
            {
                uint32_t row = (uint32_t)(wm * 16 + (lane & 15));
                uint32_t colb = (uint32_t)(ks * 32 + ((lane >> 4) << 4));
                uint32_t so = row * 128 + colb;
                so ^= (so >> 3) & 0x70;
                ldmx4(a_hi, boff + so);
                ldmx4(a_lo, boff + 8192 + so);
            }
            // B: one ldmx4 covers an nt pair (16 rows x 16 cols)
            uint32_t b_hi[4][2], b_lo[4][2];
#pragma unroll
            for (int pp = 0; pp < 2; pp++) {
                uint32_t row = (uint32_t)(wn * 32 + pp * 16 +
                                          ((lane >> 4) << 3) + (lane & 7));
                uint32_t colb = (uint32_t)(ks * 32 + (((lane >> 3) & 1) << 4));
                uint32_t so = row * 128 + colb;
                so ^= (so >> 3) & 0x70;
                uint32_t rh[4], rl[4];
                ldmx4(rh, boff + 16384 + so);
                ldmx4(rl, boff + 24576 + so);
                b_hi[2*pp][0] = rh[0]; b_hi[2*pp][1] = rh[1];
                b_hi[2*pp+1][0] = rh[2]; b_hi[2*pp+1][1] = rh[3];
                b_lo[2*pp][0] = rl[0]; b_lo[2*pp][1] = rl[1];
                b_lo[2*pp+1][0] = rl[2]; b_lo[2*pp+1][1] = rl[3];
            }
#pragma unroll
            for (int nt = 0; nt < 4; nt++) {
                mma16816(acc[nt], a_hi, b_hi[nt]);
                mma16816(acc[nt], a_hi, b_lo[nt]);
                mma16816(acc[nt], a_lo, b_hi[nt]);
            }
        }
        if (c + 2 < nchunks) {
            __syncthreads();   // buffer (c&1) free only after all warps consumed it
            mma_issue(base, c + 2, tid, m0, n0, koff, M, ah, al, wh, wl, aK, wK);
        }
    }

    // ---- epilogue: each warp writes its 16x32 tile ----
#pragma unroll
    for (int nt = 0; nt < 4; nt++) {
        int m = m0 + wm * 16 + (lane >> 2);
        int n = n0 + wn * 32 + nt * 8 + (lane & 3) * 2;
        if (m < M)
            *(float2*)(C + (size_t)m * Nn + n) = make_float2(acc[nt][0], acc[nt][1]);
        if (m + 8 < M)
            *(float2*)(C + (size_t)(m + 8) * Nn + n) = make_float2(acc[nt][2], acc[nt][3]);
    }
}

__device__ __forceinline__ void split4_store(float4 v, __nv_bfloat16* hp,
                                             __nv_bfloat16* lp, size_t off) {
    __nv_bfloat16 hh[4], ll[4];
    split_bf16(v.x, &hh[0], &ll[0]);
    split_bf16(v.y, &hh[1], &ll[1]);
    split_bf16(v.z, &hh[2], &ll[2]);
    split_bf16(v.w, &hh[3], &ll[3]);
    *(uint2*)(hp + off) = *(uint2*)hh;
    *(uint2*)(lp + off) = *(uint2*)ll;
}

// ------------------ merged prep: all weight splits + patch gather ------------------
#define NP0 (DMODEL*256/4)                  // patchw f4s   (24576)
#define NP1 (4*2*DIN*DMODEL/4)              // inpw f4s     (589824)
#define NP2 (4*DMODEL*DIN/4)                // outw f4s     (294912)
#define NP3 (BATCH*NTOK*256/4)              // patch gather (65536)
__global__ void k_prep(const float* __restrict__ patchw,
                       const float* __restrict__ inpw,
                       const float* __restrict__ outw,
                       const float* __restrict__ depth) {
    const int total = NP0 + NP1 + NP2 + NP3;
    for (int i = blockIdx.x * 256 + threadIdx.x; i < total; i += gridDim.x * 256) {
        if (i < NP0) {
            split4_store(ld4(patchw + (size_t)i * 4), gwp_hi, gwp_lo, (size_t)i * 4);
        } else if (i < NP0 + NP1) {
            size_t j = i - NP0;
            split4_store(ld4(inpw + j * 4), gwin_hi, gwin_lo, j * 4);
        } else if (i < NP0 + NP1 + NP2) {
            size_t j = i - NP0 - NP1;
            split4_store(ld4(outw + j * 4), gwout_hi, gwout_lo, j * 4);
        } else {
            int j = i - NP0 - NP1 - NP2;
            int m = j >> 6, k = (j & 63) * 4;       // row m of 256 cols, col k
            int b = m >> 8, p = m & 255;
            int ii = k >> 4, jj = k & 15;
            int gh = p >> 3, gw = p & 7;
            int row = gh * 16 + ii;
            int tt = row >> 7, hh = row & 127;
            int col = gw * 16 + jj;
            float4 v = ld4(depth + (size_t)(((b * 4 + tt) << 7) + hh) * 128 + col);
            split4_store(v, gp_hi, gp_lo, (size_t)m * 256 + k);
        }
    }
}

// combine + silu(z) gate + split  (A of out_proj, K=768), float4
__global__ void k_prepA1() {
    int m = blockIdx.x;                       // BL blocks x 192 threads
    int b = m / LQ, l = m - b * LQ;
    const float* yf = g_y[0] + (size_t)m * DIN;
    const float* yb = g_y[1] + (size_t)(b * LQ + (NTOK - l)) * DIN;
    const float* zp = g_xz + (size_t)m * (2 * DIN) + DIN;
    int k = threadIdx.x * 4;
    float4 z = ld4(zp + k), u = ld4(yf + k), v = ld4(yb + k);
    float4 x;
    x.x = (u.x + v.x) * (z.x / (1.f + __expf(-z.x)));
    x.y = (u.y + v.y) * (z.y / (1.f + __expf(-z.y)));
    x.z = (u.z + v.z) * (z.z / (1.f + __expf(-z.z)));
    x.w = (u.w + v.w) * (z.w / (1.f + __expf(-z.w)));
    split4_store(x, ga_hi, ga_lo, (size_t)m * DIN + k);
}

// ------------------ residual/assemble + LN -> split bf16 A (K=384) ------------------
// mode 0: assemble from tok/cls/pos (layer 0).  mode 1: add split-K partials.
__global__ void k_lnadd(int mode, const float* __restrict__ w,
                        const float* __restrict__ bb,
                        const float* __restrict__ cls,
                        const float* __restrict__ pos,
                        const float* __restrict__ pb) {
    int row = blockIdx.x * 8 + (threadIdx.x >> 5);
    int lane = threadIdx.x & 31;
    if (row >= BL) return;
    float* rp = g_resid + (size_t)row * DMODEL;
    float v[12];
    float s = 0.f;
    if (mode == 0) {
        int b = row / LQ, l = row - b * LQ;
#pragma unroll
        for (int q = 0; q < 12; q++) {
            int d = lane + 32 * q;
            float x;
            if (l == POSI) x = cls[d];
            else {
                int p = (l < POSI) ? l : (l - 1);
                x = g_tok[(size_t)(b * NTOK + p) * DMODEL + d] + pb[d];
            }
            x += pos[l * DMODEL + d];
            rp[d] = x;
            v[q] = x; s += x;
        }
    } else {
        const float* h0 = g_hid[0] + (size_t)row * DMODEL;
        const float* h1 = g_hid[1] + (size_t)row * DMODEL;
#pragma unroll
        for (int q = 0; q < 12; q++) {
            int d = lane + 32 * q;
            float x = rp[d] + h0[d] + h1[d];
            rp[d] = x;
            v[q] = x; s += x;
        }
    }
#pragma unroll
    for (int m = 16; m; m >>= 1) s += __shfl_xor_sync(0xffffffffu, s, m);
    float mean = s * (1.f / DMODEL);
    float sq = 0.f;
#pragma unroll
    for (int q = 0; q < 12; q++) { float dv = v[q] - mean; sq += dv * dv; }
#pragma unroll
    for (int m = 16; m; m >>= 1) sq += __shfl_xor_sync(0xffffffffu, sq, m);
    float rstd = rsqrtf(sq * (1.f / DMODEL) + 1e-5f);
#pragma unroll
    for (int q = 0; q < 12; q++) {
        int d = lane + 32 * q;
        float y = (v[q] - mean) * rstd * w[d] + bb[d];
        split_bf16(y, &ga_hi[(size_t)row * DMODEL + d],
                      &ga_lo[(size_t)row * DMODEL + d]);
    }
}

// ------------------ fused conv+silu -> xproj -> B,C -> dtproj+softplus ------------------
__global__ void k_xproj(const float* __restrict__ cwf, const float* __restrict__ cbf,
                        const float* __restrict__ cwb, const float* __restrict__ cbb,
                        const float* __restrict__ xwf, const float* __restrict__ xwb,
                        const float* __restrict__ dwf, const float* __restrict__ dbf,
                        const float* __restrict__ dwb, const float* __restrict__ dbb) {
    __shared__ __align__(16) float sxc[XR][DIN];
    __shared__ float sdb[XR * 56];
    int l0 = blockIdx.x * XR;
    int b = blockIdx.y, br = blockIdx.z;
    int tid = threadIdx.x;                 // 256
    const float* cw = br ? cwb : cwf;
    const float* cb = br ? cbb : cbf;

    // phase 0: conv + silu, sliding window over rows (each row loaded once)
    for (int d = tid; d < DIN; d += 256) {
        float4 wc = ld4(&cw[d * KCONV]);
        float wct[4] = {wc.x, wc.y, wc.z, wc.w};
        float bias = cb[d];
        float v[XR + 3];
#pragma unroll
        for (int j = 0; j < XR + 3; j++) {
            int idx = l0 - 3 + j;
            float x = 0.f;
            if (idx >= 0 && idx <= NTOK) {
                int src = br ? (NTOK - idx) : idx;
                x = g_xz[(size_t)(b * LQ + src) * (2 * DIN) + d];
            }
            v[j] = x;
        }
#pragma unroll
        for (int r = 0; r < XR; r++) {
            int l = l0 + r;
            float val = 0.f;
            if (l < LQ) {
                float acc = bias + wct[0] * v[r] + wct[1] * v[r + 1] +
                            wct[2] * v[r + 2] + wct[3] * v[r + 3];
                val = acc / (1.f + __expf(-acc));
                g_xc[br][(size_t)(b * LQ + l) * DIN + d] = val;
            }
            sxc[r][d] = val;
        }
    }
    __syncthreads();

    {
        const float* xw = br ? xwb : xwf;
        int wid = tid >> 5, lane = tid & 31;
        for (int e = wid; e < 56; e += 8) {
            float4 w4[6];
#pragma unroll
            for (int j = 0; j < 6; j++)
                w4[j] = ld4(&xw[(size_t)e * DIN + lane * 4 + 128 * j]);
#pragma unroll
            for (int r = 0; r < XR; r++) {
                float p = 0.f;
#pragma unroll
                for (int j = 0; j < 6; j++) {
                    float4 s4 = ld4(&sxc[r][lane * 4 + 128 * j]);
                    p += w4[j].x * s4.x + w4[j].y * s4.y +
                         w4[j].z * s4.z + w4[j].w * s4.w;
                }
#pragma unroll
                for (int m = 16; m; m >>= 1) p += __shfl_xor_sync(0xffffffffu, p, m);
                if (lane == 0) sdb[r * 56 + e] = p;
            }
        }
    }
    __syncthreads();

    {
        int r = tid >> 5, n = tid & 31;       // XR*32 = 256 threads exactly
        int l = l0 + r;
        if (l < LQ) g_bc[br][(size_t)(b * LQ + l) * 32 + n] = sdb[r * 56 + 24 + n];
    }

    const float* dw = br ? dwb : dwf;
    const float* db = br ? dbb : dbf;
    for (int d = tid; d < DIN; d += 256) {
        float4 w4[6];
#pragma unroll
        for (int j = 0; j < 6; j++) w4[j] = ld4(&dw[(size_t)d * DTR + j * 4]);
        float bias = db[d];
#pragma unroll
        for (int r = 0; r < XR; r++) {
            int l = l0 + r;
            if (l >= LQ) break;
            const float* sp = &sdb[r * 56];
            float acc = bias;
#pragma unroll
            for (int j = 0; j < 6; j++) {
                acc += w4[j].x * sp[j * 4 + 0] + w4[j].y * sp[j * 4 + 1] +
                       w4[j].z * sp[j * 4 + 2] + w4[j].w * sp[j * 4 + 3];
            }
            float spv = (acc > 20.f) ? acc : log1pf(__expf(acc));
            g_dt[br][(size_t)(b * LQ + l) * DIN + d] = spv;
        }
    }
}

// ------------------ selective scan: cp.async-staged dt/xc tiles ------------------
#define TS 32
#define NCH ((LQ + TS - 1) / TS)   // 9
__global__ void k_ssm(const float* __restrict__ Alf, const float* __restrict__ Alb,
                      const float* __restrict__ Dpf, const float* __restrict__ Dpb) {
    __shared__ __align__(16) float sBC[LQ][32];
    __shared__ __align__(16) float sdt[2][TS * 16];
    __shared__ __align__(16) float sxc[2][TS * 16];
    int chunk = blockIdx.x;
    int b = blockIdx.y, br = blockIdx.z;
    int tid = threadIdx.x;
    int n = tid & 15, dl = tid >> 4;
    int d = chunk * 16 + dl;
    const float4* bcb4 = (const float4*)(g_bc[br] + (size_t)b * LQ * 32);
    float4* sBC4 = (float4*)sBC;
    for (int i = tid; i < LQ * 8; i += 256) sBC4[i] = bcb4[i];
    const float* Al = br ? Alb : Alf;
    float A = -__expf(Al[(size_t)d * NST + n]);
    float Dv = (br ? Dpb : Dpf)[d];
    // row bases (without t): element 0 of this chunk's 16-d slice
    const float* dtrow = g_dt[br] + (size_t)b * LQ * DIN + chunk * 16;
    const float* xcrow = g_xc[br] + (size_t)b * LQ * DIN + chunk * 16;
    float* yp = g_y[br] + (size_t)b * LQ * DIN + d;
    uint32_t sdt_b = smem_u32(sdt), sxc_b = smem_u32(sxc);

    // issue chunk c's staging loads (128 threads dt, 128 threads xc)
    auto issue = [&](int c) {
        int buf = c & 1;
        int idx = tid & 127;
        int t = idx >> 2, seg = (idx & 3) << 2;
        int tg = c * TS + t;
        int ok = (tg < LQ) ? 16 : 0;
        size_t off = (size_t)(ok ? tg : 0) * DIN + seg;
        if (tid < 128)
            cpa16(sdt_b + (buf * TS * 16 + t * 16 + seg) * 4, dtrow + off, ok);
        else
            cpa16(sxc_b + (buf * TS * 16 + t * 16 + seg) * 4, xcrow + off, ok);
        asm volatile("cp.async.commit_group;");
    };

    issue(0);
    issue(1);

    float h = 0.f;
    for (int c = 0; c < NCH; c++) {
        if (c + 1 < NCH) asm volatile("cp.async.wait_group 1;");
        else             asm volatile("cp.async.wait_group 0;");
        __syncthreads();
        const float* dts = sdt[c & 1];
        const float* xcs = sxc[c & 1];
        int tend = (c * TS + TS <= LQ) ? TS : (LQ - c * TS);
        for (int j = 0; j < tend; j++) {
            int t = c * TS + j;
            float dtv = dts[j * 16 + dl];
            float xv  = xcs[j * 16 + dl];
            float dA = __expf(dtv * A);
            h = dA * h + dtv * sBC[t][n] * xv;
            float p = h * sBC[t][16 + n];
            p += __shfl_xor_sync(0xffffffffu, p, 8);
            p += __shfl_xor_sync(0xffffffffu, p, 4);
            p += __shfl_xor_sync(0xffffffffu, p, 2);
            p += __shfl_xor_sync(0xffffffffu, p, 1);
            if (n == 0) yp[(size_t)t * DIN] = p + xv * Dv;  // gate applied in k_prepA1
        }
        if (c + 2 < NCH) {
            __syncthreads();      // all warps done reading buffer (c&1)
            issue(c + 2);
        }
    }
}

// ------------------ final residual + LN + cmd MLP head ------------------
__global__ void k_final(const float* __restrict__ sv, const float* __restrict__ av,
                        const float* __restrict__ lnw, const float* __restrict__ lnb,
                        const float* __restrict__ cw1, const float* __restrict__ cb1,
                        const float* __restrict__ cw2, const float* __restrict__ cb2,
                        float* __restrict__ out) {
    int b = blockIdx.x, tid = threadIdx.x;   // 384 threads
    __shared__ float c1[DMODEL], svis[DMODEL], cmdv[20], red[12];
    int row = b * LQ + POSI;
    float x = g_resid[(size_t)row * DMODEL + tid] +
              g_hid[0][(size_t)row * DMODEL + tid] +
              g_hid[1][(size_t)row * DMODEL + tid];
    float s = x;
#pragma unroll
    for (int m = 16; m; m >>= 1) s += __shfl_xor_sync(0xffffffffu, s, m);
    if ((tid & 31) == 0) red[tid >> 5] = s;
    __syncthreads();
    float tot = 0.f;
#pragma unroll
    for (int i = 0; i < 12; i++) tot += red[i];
    float mean = tot * (1.0f / DMODEL);
    float dv = x - mean;
    float vsq = dv * dv;
    __syncthreads();
#pragma unroll
    for (int m = 16; m; m >>= 1) vsq += __shfl_xor_sync(0xffffffffu, vsq, m);
    if ((tid & 31) == 0) red[tid >> 5] = vsq;
    __syncthreads();
    float vt = 0.f;
#pragma unroll
    for (int i = 0; i < 12; i++) vt += red[i];
    svis[tid] = dv * rsqrtf(vt * (1.0f / DMODEL) + 1e-5f) * lnw[tid] + lnb[tid];
    if (tid < 20) cmdv[tid] = (tid < 16) ? sv[b * 16 + tid] : av[b * 4 + tid - 16];
    __syncthreads();
    float a1 = cb1[tid];
#pragma unroll
    for (int k = 0; k < 20; k++) a1 += cmdv[k] * cw1[tid * 20 + k];
    c1[tid] = fmaxf(a1, 0.f);
    __syncthreads();
    int w = tid >> 5, lane = tid & 31;
    for (int r = w; r < DMODEL; r += 12) {
        float p = 0.f;
        const float* wr = cw2 + (size_t)r * DMODEL;
#pragma unroll
        for (int j = 0; j < 12; j++) p += c1[lane + 32 * j] * wr[lane + 32 * j];
#pragma unroll
        for (int m = 16; m; m >>= 1) p += __shfl_xor_sync(0xffffffffu, p, m);
        if (lane == 0) out[b * DMODEL + r] = svis[r] + p + cb2[r];
    }
}

// ------------------ host ------------------
extern "C" void kernel_launch(void* const* d_in, const int* in_sizes, int n_in,
                              void* d_out, int out_size) {
    const float* depth  = (const float*)d_in[0];
    const float* state  = (const float*)d_in[1];
    const float* action = (const float*)d_in[2];
    const float* patchw = (const float*)d_in[3];
    const float* patchb = (const float*)d_in[4];
    const float* cls    = (const float*)d_in[5];
    const float* pos    = (const float*)d_in[6];
    const float* lnw    = (const float*)d_in[7];
    const float* lnb    = (const float*)d_in[8];
    const float* inpw   = (const float*)d_in[9];
    const float* convw  = (const float*)d_in[10];
    const float* convb  = (const float*)d_in[11];
    const float* convwb = (const float*)d_in[12];
    const float* convbb = (const float*)d_in[13];
    const float* xpw    = (const float*)d_in[14];
    const float* xpwb   = (const float*)d_in[15];
    const float* dtw    = (const float*)d_in[16];
    const float* dtbv   = (const float*)d_in[17];
    const float* dtwb   = (const float*)d_in[18];
    const float* dtbb   = (const float*)d_in[19];
    const float* Alog   = (const float*)d_in[20];
    const float* Alogb  = (const float*)d_in[21];
    const float* Dp     = (const float*)d_in[22];
    const float* Dpb    = (const float*)d_in[23];
    const float* outw   = (const float*)d_in[24];
    const float* lnfw   = (const float*)d_in[25];
    const float* lnfb   = (const float*)d_in[26];
    const float* cw1    = (const float*)d_in[27];
    const float* cb1    = (const float*)d_in[28];
    const float* cw2    = (const float*)d_in[29];
    const float* cb2    = (const float*)d_in[30];

    float *p_tok, *p_xz, *p_hid;
    __nv_bfloat16 *p_wp_hi, *p_wp_lo, *p_win_hi, *p_win_lo, *p_wout_hi, *p_wout_lo;
    __nv_bfloat16 *p_a_hi, *p_a_lo, *p_p_hi, *p_p_lo;
    cudaGetSymbolAddress((void**)&p_tok, g_tok);
    cudaGetSymbolAddress((void**)&p_xz, g_xz);
    cudaGetSymbolAddress((void**)&p_hid, g_hid);
    cudaGetSymbolAddress((void**)&p_wp_hi, gwp_hi);
    cudaGetSymbolAddress((void**)&p_wp_lo, gwp_lo);
    cudaGetSymbolAddress((void**)&p_win_hi, gwin_hi);
    cudaGetSymbolAddress((void**)&p_win_lo, gwin_lo);
    cudaGetSymbolAddress((void**)&p_wout_hi, gwout_hi);
    cudaGetSymbolAddress((void**)&p_wout_lo, gwout_lo);
    cudaGetSymbolAddress((void**)&p_a_hi, ga_hi);
    cudaGetSymbolAddress((void**)&p_a_lo, ga_lo);
    cudaGetSymbolAddress((void**)&p_p_hi, gp_hi);
    cudaGetSymbolAddress((void**)&p_p_lo, gp_lo);

    cudaFuncSetAttribute(k_mma, cudaFuncAttributeMaxDynamicSharedMemorySize, SMEM_SZ);

    // merged prep: weight splits + patch gather (1 launch)
    k_prep<<<1024, 256>>>(patchw, inpw, outw, depth);

    // patch embed: M=1024, N=384, K=256
    k_mma<<<dim3(6, 16, 1), 256, SMEM_SZ>>>(p_p_hi, p_p_lo, p_wp_hi, p_wp_lo,
                                            p_tok, BATCH * NTOK, DMODEL, 256, 256, 4);

    for (int i = 0; i < 4; i++) {
        // layer 0: assemble (tok+cls+pos) fused into lnadd mode 0
        k_lnadd<<<(BL + 7) / 8, 256>>>(i == 0 ? 0 : 1,
                                       lnw + i * DMODEL, lnb + i * DMODEL,
                                       cls, pos, patchb);
        // in_proj: M=1028, N=1536, K=384
        k_mma<<<dim3(24, 17, 1), 256, SMEM_SZ>>>(
            p_a_hi, p_a_lo,
            p_win_hi + (size_t)i * 2 * DIN * DMODEL,
            p_win_lo + (size_t)i * 2 * DIN * DMODEL,
            p_xz, BL, 2 * DIN, DMODEL, DMODEL, 6);
        k_xproj<<<dim3((LQ + XR - 1) / XR, BATCH, 2), 256>>>(
            convw + i * DIN * KCONV, convb + i * DIN,
            convwb + i * DIN * KCONV, convbb + i * DIN,
            xpw + (size_t)i * 56 * DIN, xpwb + (size_t)i * 56 * DIN,
            dtw + (size_t)i * DIN * DTR, dtbv + i * DIN,
            dtwb + (size_t)i * DIN * DTR, dtbb + i * DIN);
        k_ssm<<<dim3(DIN / 16, BATCH, 2), 256>>>(
            Alog + (size_t)i * DIN * NST, Alogb + (size_t)i * DIN * NST,
            Dp + i * DIN, Dpb + i * DIN);
        k_prepA1<<<BL, 192>>>();
        // out_proj: M=1028, N=384, K=768, split-K=2 via blockIdx.z
        k_mma<<<dim3(6, 17, 2), 256, SMEM_SZ>>>(
            p_a_hi, p_a_lo,
            p_wout_hi + (size_t)i * DMODEL * DIN,
            p_wout_lo + (size_t)i * DMODEL * DIN,
            p_hid, BL, DMODEL, DIN, DIN, 6);
    }

    k_final<<<BATCH, DMODEL>>>(state, action, lnfw, lnfb, cw1, cb1, cw2, cb2,
                               (float*)d_out);
}